// round 1
// baseline (speedup 1.0000x reference)
#include <cuda_runtime.h>
#include <math.h>

#define NN 50000
#define EE 300000
#define IN_DIM 768
#define HID 256
#define OUT_DIM 128
#define HEADS 8

// ---------------- scratch (static device globals; no allocation) ----------------
__device__ float g_H0P[NN * HID];
__device__ float g_H0A[NN * HID];
__device__ float g_SS[NN * HEADS];
__device__ float g_SD[NN * HEADS];
__device__ float g_AMAX[NN * HEADS];
__device__ float g_DEN[NN * HEADS];
__device__ float g_EX[EE * HEADS];
__device__ float g_AGG0a[NN * HID];   // writes      -> paper
__device__ float g_AGG0b[NN * HID];   // written_by  -> author
__device__ float g_AGG0c[NN * HID];   // cites       -> paper
__device__ float g_R0P[NN * HID];
__device__ float g_R0A[NN * HID];
__device__ float g_H1P[NN * OUT_DIM];
__device__ float g_H1A[NN * OUT_DIM];
__device__ float g_AGG1a[NN * OUT_DIM];
__device__ float g_AGG1b[NN * OUT_DIM];
__device__ float g_AGG1c[NN * OUT_DIM];
__device__ float g_R1P[NN * OUT_DIM];
__device__ float g_COLSUM[2 * HID];
__device__ float g_W2[2];

// ---------------- generic tiled SGEMM ----------------
// C[M,N] = A[M,K] @ B[K,N] + bias   (MODE 0: store; MODE 1: colsum += tanh(.) column sums)
// Requires: N % BN == 0, K % BK == 0. M guarded.
template <int BM, int BN, int BK, int TM, int TN, int MODE>
__global__ __launch_bounds__((BM / TM) * (BN / TN))
void sgemm_kernel(int M, int N, int K,
                  const float* __restrict__ A,
                  const float* __restrict__ B,
                  const float* __restrict__ bias,
                  float* __restrict__ C) {
    constexpr int NT = (BM / TM) * (BN / TN);
    __shared__ float As[BK][BM + 1];
    __shared__ float Bs[BK][BN];
    const int tid = threadIdx.x;
    const int block_row = blockIdx.y * BM;
    const int block_col = blockIdx.x * BN;
    const int trow = (tid / (BN / TN)) * TM;
    const int tcol = (tid % (BN / TN)) * TN;

    float acc[TM][TN];
#pragma unroll
    for (int i = 0; i < TM; i++)
#pragma unroll
        for (int j = 0; j < TN; j++) acc[i][j] = 0.f;

    const int aRow = tid / BK, aCol = tid % BK;
    constexpr int aStride = NT / BK;
    const int bRow = tid / BN, bCol = tid % BN;
    constexpr int bStride = NT / BN;

    for (int k0 = 0; k0 < K; k0 += BK) {
#pragma unroll
        for (int i = 0; i < BM; i += aStride) {
            int gr = block_row + aRow + i;
            As[aCol][aRow + i] = (gr < M) ? A[(size_t)gr * K + k0 + aCol] : 0.f;
        }
#pragma unroll
        for (int i = 0; i < BK; i += bStride) {
            Bs[bRow + i][bCol] = B[(size_t)(k0 + bRow + i) * N + block_col + bCol];
        }
        __syncthreads();
#pragma unroll
        for (int kk = 0; kk < BK; kk++) {
            float a[TM], b[TN];
#pragma unroll
            for (int i = 0; i < TM; i++) a[i] = As[kk][trow + i];
#pragma unroll
            for (int j = 0; j < TN; j++) b[j] = Bs[kk][tcol + j];
#pragma unroll
            for (int i = 0; i < TM; i++)
#pragma unroll
                for (int j = 0; j < TN; j++) acc[i][j] += a[i] * b[j];
        }
        __syncthreads();
    }

    if (MODE == 0) {
#pragma unroll
        for (int i = 0; i < TM; i++) {
            int gr = block_row + trow + i;
            if (gr < M) {
#pragma unroll
                for (int j = 0; j < TN; j++) {
                    int gc = block_col + tcol + j;
                    C[(size_t)gr * N + gc] = acc[i][j] + bias[gc];
                }
            }
        }
    } else {
        __shared__ float csum[BN];
        for (int i = tid; i < BN; i += NT) csum[i] = 0.f;
        __syncthreads();
        float cs[TN];
#pragma unroll
        for (int j = 0; j < TN; j++) cs[j] = 0.f;
#pragma unroll
        for (int i = 0; i < TM; i++) {
            int gr = block_row + trow + i;
            if (gr < M) {
#pragma unroll
                for (int j = 0; j < TN; j++) {
                    int gc = block_col + tcol + j;
                    cs[j] += tanhf(acc[i][j] + bias[gc]);
                }
            }
        }
#pragma unroll
        for (int j = 0; j < TN; j++) atomicAdd(&csum[tcol + j], cs[j]);
        __syncthreads();
        for (int i = tid; i < BN; i += NT) atomicAdd(&C[block_col + i], csum[i]);
    }
}

// ---------------- small kernels ----------------
__global__ void fill_kernel(float* __restrict__ p, float v, int n) {
    for (int i = blockIdx.x * blockDim.x + threadIdx.x; i < n; i += gridDim.x * blockDim.x)
        p[i] = v;
}

__global__ void node_scores_kernel(const float* __restrict__ H, const float* __restrict__ a,
                                   float* __restrict__ out, int n, int heads, int d) {
    int idx = blockIdx.x * blockDim.x + threadIdx.x;
    if (idx >= n * heads) return;
    int node = idx / heads, h = idx - node * heads;
    const float* row = H + (size_t)node * heads * d + h * d;
    const float* av = a + h * d;
    float s = 0.f;
    for (int i = 0; i < d; i++) s += row[i] * av[i];
    out[idx] = s;
}

__device__ __forceinline__ void atomicMaxF(float* addr, float val) {
    int old = __float_as_int(*addr);
    while (__int_as_float(old) < val) {
        int assumed = old;
        old = atomicCAS((int*)addr, assumed, __float_as_int(val));
        if (old == assumed) break;
    }
}

__device__ __forceinline__ float lrelu02(float x) { return x >= 0.f ? x : 0.2f * x; }

__global__ void edge_max_kernel(const int* __restrict__ ei,
                                const float* __restrict__ ss, const float* __restrict__ sd,
                                float* __restrict__ amax, int E, int heads) {
    int total = E * heads;
    for (int idx = blockIdx.x * blockDim.x + threadIdx.x; idx < total; idx += gridDim.x * blockDim.x) {
        int e = idx / heads, h = idx - e * heads;
        int s = ei[e], dn = ei[E + e];
        float al = lrelu02(ss[s * heads + h] + sd[dn * heads + h]);
        atomicMaxF(&amax[dn * heads + h], al);
    }
}

__global__ void edge_exp_kernel(const int* __restrict__ ei,
                                const float* __restrict__ ss, const float* __restrict__ sd,
                                const float* __restrict__ amax,
                                float* __restrict__ ex, float* __restrict__ den,
                                int E, int heads) {
    int total = E * heads;
    for (int idx = blockIdx.x * blockDim.x + threadIdx.x; idx < total; idx += gridDim.x * blockDim.x) {
        int e = idx / heads, h = idx - e * heads;
        int s = ei[e], dn = ei[E + e];
        float al = lrelu02(ss[s * heads + h] + sd[dn * heads + h]);
        float v = expf(al - amax[dn * heads + h]);
        ex[idx] = v;
        atomicAdd(&den[dn * heads + h], v);
    }
}

__global__ void edge_scatter_kernel(const int* __restrict__ ei,
                                    const float* __restrict__ ex, const float* __restrict__ den,
                                    const float* __restrict__ Hsrc, float* __restrict__ agg,
                                    int E, int heads, int C) {
    size_t total = (size_t)E * C;
    int d = C / heads;
    for (size_t idx = (size_t)blockIdx.x * blockDim.x + threadIdx.x; idx < total;
         idx += (size_t)gridDim.x * blockDim.x) {
        int e = (int)(idx / C);
        int c = (int)(idx - (size_t)e * C);
        int h = c / d;
        int s = ei[e], dn = ei[E + e];
        float alpha = ex[(size_t)e * heads + h] / (den[dn * heads + h] + 1e-16f);
        atomicAdd(&agg[(size_t)dn * C + c], Hsrc[(size_t)s * C + c] * alpha);
    }
}

__global__ void relu_kernel(float* __restrict__ p, size_t n) {
    for (size_t i = (size_t)blockIdx.x * blockDim.x + threadIdx.x; i < n;
         i += (size_t)gridDim.x * blockDim.x)
        p[i] = fmaxf(p[i], 0.f);
}

__global__ void semantic_weights_kernel(const float* __restrict__ colsum,
                                        const float* __restrict__ q,
                                        int C, float invn, float* __restrict__ w) {
    __shared__ float sh0[256], sh1[256];
    int t = threadIdx.x;
    float s0 = 0.f, s1 = 0.f;
    for (int c = t; c < C; c += blockDim.x) {
        float qc = q[c];
        s0 += qc * colsum[c];
        s1 += qc * colsum[C + c];
    }
    sh0[t] = s0; sh1[t] = s1;
    __syncthreads();
    for (int o = blockDim.x / 2; o > 0; o >>= 1) {
        if (t < o) { sh0[t] += sh0[t + o]; sh1[t] += sh1[t + o]; }
        __syncthreads();
    }
    if (t == 0) {
        float a = sh0[0] * invn, b = sh1[0] * invn;
        float m = fmaxf(a, b);
        float ea = expf(a - m), eb = expf(b - m);
        float inv = 1.f / (ea + eb);
        w[0] = ea * inv; w[1] = eb * inv;
    }
}

__global__ void combine2_kernel(const float* __restrict__ A, const float* __restrict__ B,
                                const float* __restrict__ w, float* __restrict__ out,
                                size_t n, int do_elu) {
    float w0 = w[0], w1 = w[1];
    for (size_t i = (size_t)blockIdx.x * blockDim.x + threadIdx.x; i < n;
         i += (size_t)gridDim.x * blockDim.x) {
        float v = w0 * A[i] + w1 * B[i];
        if (do_elu) v = v > 0.f ? v : expm1f(v);
        out[i] = v;
    }
}

__global__ void elu_copy_kernel(const float* __restrict__ in, float* __restrict__ out, size_t n) {
    for (size_t i = (size_t)blockIdx.x * blockDim.x + threadIdx.x; i < n;
         i += (size_t)gridDim.x * blockDim.x) {
        float v = in[i];
        out[i] = v > 0.f ? v : expm1f(v);
    }
}

__global__ void l2norm_kernel(const float* __restrict__ in, float* __restrict__ out, int C) {
    __shared__ float sh[128];
    int row = blockIdx.x;
    int t = threadIdx.x;
    float v = in[(size_t)row * C + t];
    sh[t] = v * v;
    __syncthreads();
    for (int o = 64; o > 0; o >>= 1) {
        if (t < o) sh[t] += sh[t + o];
        __syncthreads();
    }
    float nrm = fmaxf(sqrtf(sh[0]), 1e-12f);
    out[(size_t)row * C + t] = v / nrm;
}

// ---------------- host orchestration ----------------
enum {
    L_XP, L_XA, L_W0P, L_B0P, L_W0A, L_B0A,
    L_A0S_W, L_A0D_W, L_A0S_WB, L_A0D_WB, L_A0S_C, L_A0D_C,
    L_WK0, L_BK0, L_Q0,
    L_W1P, L_B1P, L_W1A, L_B1A,
    L_A1S_W, L_A1D_W, L_A1S_WB, L_A1D_WB, L_A1S_C, L_A1D_C,
    L_WK1, L_BK1, L_Q1, L_EIW, L_EIWB, L_EIC, L_COUNT
};

extern "C" void kernel_launch(void* const* d_in, const int* in_sizes, int n_in,
                              void* d_out, int out_size) {
    // Input-order detection: dict order has edge indices at slots 2..4.
    static const int mapSig[L_COUNT] = {
        0, 1, 2, 3, 4, 5, 6, 7, 8, 9, 10, 11, 12, 13, 14,
        15, 16, 17, 18, 19, 20, 21, 22, 23, 24, 25, 26, 27, 28, 29, 30};
    static const int mapDict[L_COUNT] = {
        0, 1, 5, 6, 7, 8, 9, 10, 11, 12, 13, 14, 15, 16, 17,
        18, 19, 20, 21, 22, 23, 24, 25, 26, 27, 28, 29, 30, 2, 3, 4};
    const int* mp = (n_in > 2 && in_sizes[2] == 2 * EE) ? mapDict : mapSig;

    const float* in_f[L_COUNT];
    for (int i = 0; i < L_COUNT; i++) in_f[i] = (const float*)d_in[mp[i]];
    const int* eiW  = (const int*)d_in[mp[L_EIW]];
    const int* eiWB = (const int*)d_in[mp[L_EIWB]];
    const int* eiC  = (const int*)d_in[mp[L_EIC]];

    float *H0P, *H0A, *SS, *SD, *AMAX, *DEN, *EX;
    float *AGG0a, *AGG0b, *AGG0c, *R0P, *R0A;
    float *H1P, *H1A, *AGG1a, *AGG1b, *AGG1c, *R1P, *COLSUM, *W2;
    cudaGetSymbolAddress((void**)&H0P, g_H0P);
    cudaGetSymbolAddress((void**)&H0A, g_H0A);
    cudaGetSymbolAddress((void**)&SS, g_SS);
    cudaGetSymbolAddress((void**)&SD, g_SD);
    cudaGetSymbolAddress((void**)&AMAX, g_AMAX);
    cudaGetSymbolAddress((void**)&DEN, g_DEN);
    cudaGetSymbolAddress((void**)&EX, g_EX);
    cudaGetSymbolAddress((void**)&AGG0a, g_AGG0a);
    cudaGetSymbolAddress((void**)&AGG0b, g_AGG0b);
    cudaGetSymbolAddress((void**)&AGG0c, g_AGG0c);
    cudaGetSymbolAddress((void**)&R0P, g_R0P);
    cudaGetSymbolAddress((void**)&R0A, g_R0A);
    cudaGetSymbolAddress((void**)&H1P, g_H1P);
    cudaGetSymbolAddress((void**)&H1A, g_H1A);
    cudaGetSymbolAddress((void**)&AGG1a, g_AGG1a);
    cudaGetSymbolAddress((void**)&AGG1b, g_AGG1b);
    cudaGetSymbolAddress((void**)&AGG1c, g_AGG1c);
    cudaGetSymbolAddress((void**)&R1P, g_R1P);
    cudaGetSymbolAddress((void**)&COLSUM, g_COLSUM);
    cudaGetSymbolAddress((void**)&W2, g_W2);

    const int TPB = 256;
    dim3 gProj0(HID / 64, (NN + 63) / 64);      // N=256
    dim3 gSem0(HID / 64, (NN + 63) / 64);
    dim3 gProj1(OUT_DIM / 64, (NN + 63) / 64);  // N=128
    dim3 gSem1(OUT_DIM / 64, (NN + 63) / 64);

    // ---------- Layer 0 projections ----------
    sgemm_kernel<64, 64, 16, 4, 4, 0><<<gProj0, TPB>>>(NN, HID, IN_DIM,
        in_f[L_XP], in_f[L_W0P], in_f[L_B0P], H0P);
    sgemm_kernel<64, 64, 16, 4, 4, 0><<<gProj0, TPB>>>(NN, HID, IN_DIM,
        in_f[L_XA], in_f[L_W0A], in_f[L_B0A], H0A);

    auto run_rel = [&](const int* ei, const float* Hsrc, const float* Hdst,
                       const float* a_s, const float* a_d, float* agg,
                       int heads, int C) {
        int d = C / heads;
        int nh = NN * heads;
        node_scores_kernel<<<(nh + TPB - 1) / TPB, TPB>>>(Hsrc, a_s, SS, NN, heads, d);
        node_scores_kernel<<<(nh + TPB - 1) / TPB, TPB>>>(Hdst, a_d, SD, NN, heads, d);
        fill_kernel<<<1024, TPB>>>(AMAX, -3e38f, nh);
        cudaMemsetAsync(DEN, 0, (size_t)nh * sizeof(float));
        edge_max_kernel<<<4096, TPB>>>(ei, SS, SD, AMAX, EE, heads);
        edge_exp_kernel<<<4096, TPB>>>(ei, SS, SD, AMAX, EX, DEN, EE, heads);
        cudaMemsetAsync(agg, 0, (size_t)NN * C * sizeof(float));
        edge_scatter_kernel<<<8192, TPB>>>(ei, EX, DEN, Hsrc, agg, EE, heads, C);
        relu_kernel<<<4096, TPB>>>(agg, (size_t)NN * C);
    };

    // ---------- Layer 0 edge relations ----------
    run_rel(eiW,  H0A, H0P, in_f[L_A0S_W],  in_f[L_A0D_W],  AGG0a, HEADS, HID);  // writes -> paper
    run_rel(eiWB, H0P, H0A, in_f[L_A0S_WB], in_f[L_A0D_WB], AGG0b, HEADS, HID);  // written_by -> author
    run_rel(eiC,  H0P, H0P, in_f[L_A0S_C],  in_f[L_A0D_C],  AGG0c, HEADS, HID);  // cites -> paper

    // ---------- Layer 0 semantic attention (paper: 2 metapaths) ----------
    cudaMemsetAsync(COLSUM, 0, 2 * HID * sizeof(float));
    sgemm_kernel<64, 64, 16, 4, 4, 1><<<gSem0, TPB>>>(NN, HID, HID,
        AGG0a, in_f[L_WK0], in_f[L_BK0], COLSUM);
    sgemm_kernel<64, 64, 16, 4, 4, 1><<<gSem0, TPB>>>(NN, HID, HID,
        AGG0c, in_f[L_WK0], in_f[L_BK0], COLSUM + HID);
    semantic_weights_kernel<<<1, 256>>>(COLSUM, in_f[L_Q0], HID, 1.f / NN, W2);
    combine2_kernel<<<4096, TPB>>>(AGG0a, AGG0c, W2, R0P, (size_t)NN * HID, 1);
    // author: single metapath -> weight 1; apply elu
    elu_copy_kernel<<<4096, TPB>>>(AGG0b, R0A, (size_t)NN * HID);

    // ---------- Layer 1 projections ----------
    sgemm_kernel<64, 64, 16, 4, 4, 0><<<gProj1, TPB>>>(NN, OUT_DIM, HID,
        R0P, in_f[L_W1P], in_f[L_B1P], H1P);
    sgemm_kernel<64, 64, 16, 4, 4, 0><<<gProj1, TPB>>>(NN, OUT_DIM, HID,
        R0A, in_f[L_W1A], in_f[L_B1A], H1A);

    // ---------- Layer 1 edge relations (heads=1, C=128) ----------
    run_rel(eiW,  H1A, H1P, in_f[L_A1S_W],  in_f[L_A1D_W],  AGG1a, 1, OUT_DIM);
    run_rel(eiWB, H1P, H1A, in_f[L_A1S_WB], in_f[L_A1D_WB], AGG1b, 1, OUT_DIM);
    run_rel(eiC,  H1P, H1P, in_f[L_A1S_C],  in_f[L_A1D_C],  AGG1c, 1, OUT_DIM);

    // ---------- Layer 1 semantic attention ----------
    cudaMemsetAsync(COLSUM, 0, 2 * OUT_DIM * sizeof(float));
    sgemm_kernel<64, 64, 16, 4, 4, 1><<<gSem1, TPB>>>(NN, OUT_DIM, OUT_DIM,
        AGG1a, in_f[L_WK1], in_f[L_BK1], COLSUM);
    sgemm_kernel<64, 64, 16, 4, 4, 1><<<gSem1, TPB>>>(NN, OUT_DIM, OUT_DIM,
        AGG1c, in_f[L_WK1], in_f[L_BK1], COLSUM + OUT_DIM);
    semantic_weights_kernel<<<1, 256>>>(COLSUM, in_f[L_Q1], OUT_DIM, 1.f / NN, W2);
    combine2_kernel<<<4096, TPB>>>(AGG1a, AGG1c, W2, R1P, (size_t)NN * OUT_DIM, 0);

    // ---------- final l2 normalize -> output (paper then author) ----------
    float* out = (float*)d_out;
    l2norm_kernel<<<NN, OUT_DIM>>>(R1P, out, OUT_DIM);
    l2norm_kernel<<<NN, OUT_DIM>>>(AGG1b, out + (size_t)NN * OUT_DIM, OUT_DIM);
}

// round 2
// speedup vs baseline: 3.2176x; 3.2176x over previous
#include <cuda_runtime.h>
#include <math.h>
#include <stdint.h>

#define NN 50000
#define EE 300000
#define IN_DIM 768
#define HID 256
#define OUT_DIM 128
#define HEADS 8

// ---------------- scratch (static device globals; no allocation) ----------------
__device__ float g_H0P[NN * HID];
__device__ float g_H0A[NN * HID];
__device__ float g_SC[6][NN * HEADS];   // per-relation src/dst scores
__device__ float g_DEN[NN * HEADS];
__device__ float g_AGG0a[NN * HID];     // writes      -> paper
__device__ float g_AGG0b[NN * HID];     // written_by  -> author
__device__ float g_AGG0c[NN * HID];     // cites       -> paper
__device__ float g_R0P[NN * HID];
__device__ float g_H1P[NN * OUT_DIM];
__device__ float g_H1A[NN * OUT_DIM];
__device__ float g_AGG1a[NN * OUT_DIM];
__device__ float g_AGG1b[NN * OUT_DIM];
__device__ float g_AGG1c[NN * OUT_DIM];
__device__ float g_R1P[NN * OUT_DIM];
__device__ float g_COLSUM[2 * HID];
__device__ float g_W2[2];

// ---------------- TF32 tensor-core GEMM ----------------
__device__ __forceinline__ uint32_t f2tf32(float x) {
    uint32_t r;
    asm("cvt.rna.tf32.f32 %0, %1;" : "=r"(r) : "f"(x));
    return r;
}

__device__ __forceinline__ void mma_tf32(float* d, const uint32_t* a, const uint32_t* b) {
    asm volatile(
        "mma.sync.aligned.m16n8k8.row.col.f32.tf32.tf32.f32 "
        "{%0,%1,%2,%3},{%4,%5,%6,%7},{%8,%9},{%0,%1,%2,%3};"
        : "+f"(d[0]), "+f"(d[1]), "+f"(d[2]), "+f"(d[3])
        : "r"(a[0]), "r"(a[1]), "r"(a[2]), "r"(a[3]), "r"(b[0]), "r"(b[1]));
}

// C[M,N] = A[M,K] @ B[K,N] + bias.
// MODE 0: store. MODE 1: atomically accumulate column sums of tanh(.) into C[N].
// RELU_A: apply relu to A elements on load.
// Requires N % 128 == 0, K % 32 == 0.
template <int MODE, int RELU_A>
__global__ __launch_bounds__(256)
void mma_gemm(int M, int N, int K,
              const float* __restrict__ A, const float* __restrict__ B,
              const float* __restrict__ bias, float* __restrict__ C) {
    __shared__ uint32_t As[128][36];   // pad 4: conflict-free a-frag reads
    __shared__ uint32_t Bs[32][136];   // pad 8: conflict-free b-frag reads

    const int tid = threadIdx.x;
    const int lane = tid & 31;
    const int warp = tid >> 5;
    const int wm = warp & 3;            // 4 warps along M
    const int wn = warp >> 2;           // 2 warps along N
    const int block_row = blockIdx.y * 128;
    const int block_col = blockIdx.x * 128;

    const int arow = tid >> 3, acol = (tid & 7) * 4;
    const int brow = tid >> 5, bcol = (tid & 31) * 4;

    float acc[2][8][4];
#pragma unroll
    for (int mt = 0; mt < 2; mt++)
#pragma unroll
        for (int nt = 0; nt < 8; nt++)
#pragma unroll
            for (int r = 0; r < 4; r++) acc[mt][nt][r] = 0.f;

    for (int k0 = 0; k0 < K; k0 += 32) {
#pragma unroll
        for (int i = 0; i < 4; i++) {
            int r = arow + 32 * i;
            int gr = block_row + r;
            float4 v = make_float4(0.f, 0.f, 0.f, 0.f);
            if (gr < M) v = *(const float4*)(A + (size_t)gr * K + k0 + acol);
            if (RELU_A) {
                v.x = fmaxf(v.x, 0.f); v.y = fmaxf(v.y, 0.f);
                v.z = fmaxf(v.z, 0.f); v.w = fmaxf(v.w, 0.f);
            }
            As[r][acol + 0] = f2tf32(v.x); As[r][acol + 1] = f2tf32(v.y);
            As[r][acol + 2] = f2tf32(v.z); As[r][acol + 3] = f2tf32(v.w);
        }
#pragma unroll
        for (int i = 0; i < 4; i++) {
            int r = brow + 8 * i;
            float4 v = *(const float4*)(B + (size_t)(k0 + r) * N + block_col + bcol);
            Bs[r][bcol + 0] = f2tf32(v.x); Bs[r][bcol + 1] = f2tf32(v.y);
            Bs[r][bcol + 2] = f2tf32(v.z); Bs[r][bcol + 3] = f2tf32(v.w);
        }
        __syncthreads();
#pragma unroll
        for (int k8 = 0; k8 < 32; k8 += 8) {
            uint32_t af[2][4], bf[8][2];
#pragma unroll
            for (int mt = 0; mt < 2; mt++) {
                int r0 = wm * 32 + mt * 16 + (lane >> 2);
                int c0 = k8 + (lane & 3);
                af[mt][0] = As[r0][c0];
                af[mt][1] = As[r0 + 8][c0];
                af[mt][2] = As[r0][c0 + 4];
                af[mt][3] = As[r0 + 8][c0 + 4];
            }
#pragma unroll
            for (int nt = 0; nt < 8; nt++) {
                int n = wn * 64 + nt * 8 + (lane >> 2);
                bf[nt][0] = Bs[k8 + (lane & 3)][n];
                bf[nt][1] = Bs[k8 + 4 + (lane & 3)][n];
            }
#pragma unroll
            for (int mt = 0; mt < 2; mt++)
#pragma unroll
                for (int nt = 0; nt < 8; nt++) mma_tf32(acc[mt][nt], af[mt], bf[nt]);
        }
        __syncthreads();
    }

    if (MODE == 0) {
#pragma unroll
        for (int mt = 0; mt < 2; mt++) {
            int r0 = block_row + wm * 32 + mt * 16 + (lane >> 2);
#pragma unroll
            for (int nt = 0; nt < 8; nt++) {
                int c0 = block_col + wn * 64 + nt * 8 + 2 * (lane & 3);
                if (r0 < M) {
                    C[(size_t)r0 * N + c0]     = acc[mt][nt][0] + bias[c0];
                    C[(size_t)r0 * N + c0 + 1] = acc[mt][nt][1] + bias[c0 + 1];
                }
                if (r0 + 8 < M) {
                    C[(size_t)(r0 + 8) * N + c0]     = acc[mt][nt][2] + bias[c0];
                    C[(size_t)(r0 + 8) * N + c0 + 1] = acc[mt][nt][3] + bias[c0 + 1];
                }
            }
        }
    } else {
        __shared__ float csum[128];
        if (tid < 128) csum[tid] = 0.f;
        __syncthreads();
#pragma unroll
        for (int nt = 0; nt < 8; nt++) {
            int cl = wn * 64 + nt * 8 + 2 * (lane & 3);
            int cg = block_col + cl;
            float l0 = 0.f, l1 = 0.f;
#pragma unroll
            for (int mt = 0; mt < 2; mt++) {
                int r0 = block_row + wm * 32 + mt * 16 + (lane >> 2);
                if (r0 < M) {
                    l0 += tanhf(acc[mt][nt][0] + bias[cg]);
                    l1 += tanhf(acc[mt][nt][1] + bias[cg + 1]);
                }
                if (r0 + 8 < M) {
                    l0 += tanhf(acc[mt][nt][2] + bias[cg]);
                    l1 += tanhf(acc[mt][nt][3] + bias[cg + 1]);
                }
            }
            atomicAdd(&csum[cl], l0);
            atomicAdd(&csum[cl + 1], l1);
        }
        __syncthreads();
        if (tid < 128) atomicAdd(&C[block_col + tid], csum[tid]);
    }
}

// ---------------- fused per-node attention scores ----------------
// One warp per node; computes up to 4 score vectors (dot per head) in one pass over H.
template <int C, int HEADS_T>
__global__ void scores_multi(const float* __restrict__ H,
                             const float* __restrict__ a0, const float* __restrict__ a1,
                             const float* __restrict__ a2, const float* __restrict__ a3,
                             float* __restrict__ o0, float* __restrict__ o1,
                             float* __restrict__ o2, float* __restrict__ o3,
                             int nA, int n) {
    int w = (blockIdx.x * blockDim.x + threadIdx.x) >> 5;
    if (w >= n) return;
    int lane = threadIdx.x & 31;
    constexpr int EPL = C / 32;          // elements per lane
    constexpr int G = 32 / HEADS_T;      // lanes per head

    float h[EPL];
    const float* row = H + (size_t)w * C + lane * EPL;
#pragma unroll
    for (int j = 0; j < EPL; j += 4) {
        float4 v = *(const float4*)(row + j);
        h[j] = v.x; h[j + 1] = v.y; h[j + 2] = v.z; h[j + 3] = v.w;
    }
    const float* av[4] = {a0, a1, a2, a3};
    float* ov[4] = {o0, o1, o2, o3};
#pragma unroll
    for (int k = 0; k < 4; k++) {
        if (k >= nA) break;
        const float* a = av[k] + lane * EPL;
        float s = 0.f;
#pragma unroll
        for (int j = 0; j < EPL; j += 4) {
            float4 v = *(const float4*)(a + j);
            s += h[j] * v.x + h[j + 1] * v.y + h[j + 2] * v.z + h[j + 3] * v.w;
        }
#pragma unroll
        for (int off = 1; off < G; off <<= 1) s += __shfl_xor_sync(0xffffffffu, s, off);
        if ((lane & (G - 1)) == 0) ov[k][w * HEADS_T + lane / G] = s;
    }
}

// ---------------- edge kernels ----------------
__device__ __forceinline__ float lrelu02(float x) { return x >= 0.f ? x : 0.2f * x; }

template <int HEADS_T>
__global__ void edge_den_kernel(const int* __restrict__ ei,
                                const float* __restrict__ ss, const float* __restrict__ sd,
                                float* __restrict__ den, int E) {
    int idx = blockIdx.x * blockDim.x + threadIdx.x;
    if (idx >= E * HEADS_T) return;
    int e = idx / HEADS_T, h = idx - e * HEADS_T;
    int s = ei[e], d = ei[E + e];
    float al = lrelu02(ss[s * HEADS_T + h] + sd[d * HEADS_T + h]);
    atomicAdd(&den[d * HEADS_T + h], expf(fminf(al, 80.f)));
}

__device__ __forceinline__ void red_add_v4(float* p, float4 v) {
    asm volatile("red.global.add.v4.f32 [%0], {%1,%2,%3,%4};"
                 :: "l"(p), "f"(v.x), "f"(v.y), "f"(v.z), "f"(v.w) : "memory");
}

template <int C, int HEADS_T>
__global__ void edge_scatter_kernel(const int* __restrict__ ei,
                                    const float* __restrict__ ss, const float* __restrict__ sd,
                                    const float* __restrict__ den,
                                    const float* __restrict__ Hsrc, float* __restrict__ agg,
                                    int E) {
    constexpr int C4 = C / 4;
    constexpr int D = C / HEADS_T;
    long long idx = (long long)blockIdx.x * blockDim.x + threadIdx.x;
    if (idx >= (long long)E * C4) return;
    int e = (int)(idx / C4);
    int c4 = (int)(idx - (long long)e * C4);
    int c = c4 * 4;
    int h = c / D;
    int s = ei[e], d = ei[E + e];
    float al = lrelu02(ss[s * HEADS_T + h] + sd[d * HEADS_T + h]);
    float alpha = expf(fminf(al, 80.f)) / (den[d * HEADS_T + h] + 1e-16f);
    float4 v = *(const float4*)(Hsrc + (size_t)s * C + c);
    v.x *= alpha; v.y *= alpha; v.z *= alpha; v.w *= alpha;
    red_add_v4(agg + (size_t)d * C + c, v);
}

// ---------------- small kernels ----------------
__global__ void semantic_weights_kernel(const float* __restrict__ colsum,
                                        const float* __restrict__ q,
                                        int C, float invn, float* __restrict__ w) {
    __shared__ float sh0[256], sh1[256];
    int t = threadIdx.x;
    float s0 = 0.f, s1 = 0.f;
    for (int c = t; c < C; c += blockDim.x) {
        float qc = q[c];
        s0 += qc * colsum[c];
        s1 += qc * colsum[C + c];
    }
    sh0[t] = s0; sh1[t] = s1;
    __syncthreads();
    for (int o = blockDim.x / 2; o > 0; o >>= 1) {
        if (t < o) { sh0[t] += sh0[t + o]; sh1[t] += sh1[t + o]; }
        __syncthreads();
    }
    if (t == 0) {
        float a = sh0[0] * invn, b = sh1[0] * invn;
        float m = fmaxf(a, b);
        float ea = expf(a - m), eb = expf(b - m);
        float inv = 1.f / (ea + eb);
        w[0] = ea * inv; w[1] = eb * inv;
    }
}

// out = w0*relu(A) + w1*relu(B), float4
__global__ void combine2_kernel(const float* __restrict__ A, const float* __restrict__ B,
                                const float* __restrict__ w, float* __restrict__ out,
                                long long n4) {
    long long i = (long long)blockIdx.x * blockDim.x + threadIdx.x;
    if (i >= n4) return;
    float w0 = w[0], w1 = w[1];
    float4 a = ((const float4*)A)[i];
    float4 b = ((const float4*)B)[i];
    float4 r;
    r.x = w0 * fmaxf(a.x, 0.f) + w1 * fmaxf(b.x, 0.f);
    r.y = w0 * fmaxf(a.y, 0.f) + w1 * fmaxf(b.y, 0.f);
    r.z = w0 * fmaxf(a.z, 0.f) + w1 * fmaxf(b.z, 0.f);
    r.w = w0 * fmaxf(a.w, 0.f) + w1 * fmaxf(b.w, 0.f);
    ((float4*)out)[i] = r;
}

// warp per row of 128; optional relu before normalizing
__global__ void l2norm_kernel(const float* __restrict__ in, float* __restrict__ out,
                              int n, int relu) {
    int w = (blockIdx.x * blockDim.x + threadIdx.x) >> 5;
    if (w >= n) return;
    int lane = threadIdx.x & 31;
    float4 v = *(const float4*)(in + (size_t)w * 128 + lane * 4);
    if (relu) {
        v.x = fmaxf(v.x, 0.f); v.y = fmaxf(v.y, 0.f);
        v.z = fmaxf(v.z, 0.f); v.w = fmaxf(v.w, 0.f);
    }
    float s = v.x * v.x + v.y * v.y + v.z * v.z + v.w * v.w;
#pragma unroll
    for (int off = 16; off > 0; off >>= 1) s += __shfl_xor_sync(0xffffffffu, s, off);
    float inv = 1.f / fmaxf(sqrtf(s), 1e-12f);
    v.x *= inv; v.y *= inv; v.z *= inv; v.w *= inv;
    *(float4*)(out + (size_t)w * 128 + lane * 4) = v;
}

// ---------------- host orchestration ----------------
enum {
    L_XP, L_XA, L_W0P, L_B0P, L_W0A, L_B0A,
    L_A0S_W, L_A0D_W, L_A0S_WB, L_A0D_WB, L_A0S_C, L_A0D_C,
    L_WK0, L_BK0, L_Q0,
    L_W1P, L_B1P, L_W1A, L_B1A,
    L_A1S_W, L_A1D_W, L_A1S_WB, L_A1D_WB, L_A1S_C, L_A1D_C,
    L_WK1, L_BK1, L_Q1, L_EIW, L_EIWB, L_EIC, L_COUNT
};

extern "C" void kernel_launch(void* const* d_in, const int* in_sizes, int n_in,
                              void* d_out, int out_size) {
    static const int mapSig[L_COUNT] = {
        0, 1, 2, 3, 4, 5, 6, 7, 8, 9, 10, 11, 12, 13, 14,
        15, 16, 17, 18, 19, 20, 21, 22, 23, 24, 25, 26, 27, 28, 29, 30};
    static const int mapDict[L_COUNT] = {
        0, 1, 5, 6, 7, 8, 9, 10, 11, 12, 13, 14, 15, 16, 17,
        18, 19, 20, 21, 22, 23, 24, 25, 26, 27, 28, 29, 30, 2, 3, 4};
    const int* mp = (n_in > 2 && in_sizes[2] == 2 * EE) ? mapDict : mapSig;

    const float* in_f[L_COUNT];
    for (int i = 0; i < L_COUNT; i++) in_f[i] = (const float*)d_in[mp[i]];
    const int* eiW  = (const int*)d_in[mp[L_EIW]];
    const int* eiWB = (const int*)d_in[mp[L_EIWB]];
    const int* eiC  = (const int*)d_in[mp[L_EIC]];

    float *H0P, *H0A, *SC, *DEN;
    float *AGG0a, *AGG0b, *AGG0c, *R0P;
    float *H1P, *H1A, *AGG1a, *AGG1b, *AGG1c, *R1P, *COLSUM, *W2;
    cudaGetSymbolAddress((void**)&H0P, g_H0P);
    cudaGetSymbolAddress((void**)&H0A, g_H0A);
    cudaGetSymbolAddress((void**)&SC, g_SC);
    cudaGetSymbolAddress((void**)&DEN, g_DEN);
    cudaGetSymbolAddress((void**)&AGG0a, g_AGG0a);
    cudaGetSymbolAddress((void**)&AGG0b, g_AGG0b);
    cudaGetSymbolAddress((void**)&AGG0c, g_AGG0c);
    cudaGetSymbolAddress((void**)&R0P, g_R0P);
    cudaGetSymbolAddress((void**)&H1P, g_H1P);
    cudaGetSymbolAddress((void**)&H1A, g_H1A);
    cudaGetSymbolAddress((void**)&AGG1a, g_AGG1a);
    cudaGetSymbolAddress((void**)&AGG1b, g_AGG1b);
    cudaGetSymbolAddress((void**)&AGG1c, g_AGG1c);
    cudaGetSymbolAddress((void**)&R1P, g_R1P);
    cudaGetSymbolAddress((void**)&COLSUM, g_COLSUM);
    cudaGetSymbolAddress((void**)&W2, g_W2);

    // score slots: [0]=ss_w [1]=sd_w [2]=ss_wb [3]=sd_wb [4]=ss_c [5]=sd_c
    float* S0 = SC + 0 * (NN * HEADS);
    float* S1 = SC + 1 * (NN * HEADS);
    float* S2 = SC + 2 * (NN * HEADS);
    float* S3 = SC + 3 * (NN * HEADS);
    float* S4 = SC + 4 * (NN * HEADS);
    float* S5 = SC + 5 * (NN * HEADS);

    const int TPB = 256;
    dim3 gGemm256(2, (NN + 127) / 128);   // N=256
    dim3 gGemm128(1, (NN + 127) / 128);   // N=128
    int scoreBlocks = (NN + 7) / 8;       // 8 warps per block, warp per node

    // ======== Layer 0 ========
    mma_gemm<0, 0><<<gGemm256, TPB>>>(NN, HID, IN_DIM, in_f[L_XP], in_f[L_W0P], in_f[L_B0P], H0P);
    mma_gemm<0, 0><<<gGemm256, TPB>>>(NN, HID, IN_DIM, in_f[L_XA], in_f[L_W0A], in_f[L_B0A], H0A);

    // scores from H0P: sd_w, ss_wb, ss_c, sd_c ; from H0A: ss_w, sd_wb
    scores_multi<HID, HEADS><<<scoreBlocks, TPB>>>(H0P,
        in_f[L_A0D_W], in_f[L_A0S_WB], in_f[L_A0S_C], in_f[L_A0D_C],
        S1, S2, S4, S5, 4, NN);
    scores_multi<HID, HEADS><<<scoreBlocks, TPB>>>(H0A,
        in_f[L_A0S_W], in_f[L_A0D_WB], in_f[L_A0S_W], in_f[L_A0S_W],
        S0, S3, S0, S0, 2, NN);

    auto run_rel0 = [&](const int* ei, const float* Hsrc, const float* ss, const float* sd,
                        float* agg) {
        cudaMemsetAsync(DEN, 0, (size_t)NN * HEADS * sizeof(float));
        edge_den_kernel<HEADS><<<(EE * HEADS + TPB - 1) / TPB, TPB>>>(ei, ss, sd, DEN, EE);
        cudaMemsetAsync(agg, 0, (size_t)NN * HID * sizeof(float));
        long long tot = (long long)EE * (HID / 4);
        edge_scatter_kernel<HID, HEADS><<<(int)((tot + TPB - 1) / TPB), TPB>>>(
            ei, ss, sd, DEN, Hsrc, agg, EE);
    };
    run_rel0(eiW,  H0A, S0, S1, AGG0a);   // author -writes-> paper
    run_rel0(eiWB, H0P, S2, S3, AGG0b);   // paper -written_by-> author
    run_rel0(eiC,  H0P, S4, S5, AGG0c);   // paper -cites-> paper

    // semantic attention (paper: writes vs cites), relu folded into A loads
    cudaMemsetAsync(COLSUM, 0, 2 * HID * sizeof(float));
    mma_gemm<1, 1><<<gGemm256, TPB>>>(NN, HID, HID, AGG0a, in_f[L_WK0], in_f[L_BK0], COLSUM);
    mma_gemm<1, 1><<<gGemm256, TPB>>>(NN, HID, HID, AGG0c, in_f[L_WK0], in_f[L_BK0], COLSUM + HID);
    semantic_weights_kernel<<<1, 256>>>(COLSUM, in_f[L_Q0], HID, 1.f / NN, W2);
    combine2_kernel<<<(int)(((long long)NN * HID / 4 + TPB - 1) / TPB), TPB>>>(
        AGG0a, AGG0c, W2, R0P, (long long)NN * HID / 4);
    // author output of layer0 = relu(AGG0b); elu is identity on non-negatives.

    // ======== Layer 1 ========
    mma_gemm<0, 0><<<gGemm128, TPB>>>(NN, OUT_DIM, HID, R0P, in_f[L_W1P], in_f[L_B1P], H1P);
    mma_gemm<0, 1><<<gGemm128, TPB>>>(NN, OUT_DIM, HID, AGG0b, in_f[L_W1A], in_f[L_B1A], H1A);

    scores_multi<OUT_DIM, 1><<<scoreBlocks, TPB>>>(H1P,
        in_f[L_A1D_W], in_f[L_A1S_WB], in_f[L_A1S_C], in_f[L_A1D_C],
        S1, S2, S4, S5, 4, NN);
    scores_multi<OUT_DIM, 1><<<scoreBlocks, TPB>>>(H1A,
        in_f[L_A1S_W], in_f[L_A1D_WB], in_f[L_A1S_W], in_f[L_A1S_W],
        S0, S3, S0, S0, 2, NN);

    auto run_rel1 = [&](const int* ei, const float* Hsrc, const float* ss, const float* sd,
                        float* agg) {
        cudaMemsetAsync(DEN, 0, (size_t)NN * sizeof(float));
        edge_den_kernel<1><<<(EE + TPB - 1) / TPB, TPB>>>(ei, ss, sd, DEN, EE);
        cudaMemsetAsync(agg, 0, (size_t)NN * OUT_DIM * sizeof(float));
        long long tot = (long long)EE * (OUT_DIM / 4);
        edge_scatter_kernel<OUT_DIM, 1><<<(int)((tot + TPB - 1) / TPB), TPB>>>(
            ei, ss, sd, DEN, Hsrc, agg, EE);
    };
    run_rel1(eiW,  H1A, S0, S1, AGG1a);
    run_rel1(eiWB, H1P, S2, S3, AGG1b);
    run_rel1(eiC,  H1P, S4, S5, AGG1c);

    cudaMemsetAsync(COLSUM, 0, 2 * OUT_DIM * sizeof(float));
    mma_gemm<1, 1><<<gGemm128, TPB>>>(NN, OUT_DIM, OUT_DIM, AGG1a, in_f[L_WK1], in_f[L_BK1], COLSUM);
    mma_gemm<1, 1><<<gGemm128, TPB>>>(NN, OUT_DIM, OUT_DIM, AGG1c, in_f[L_WK1], in_f[L_BK1], COLSUM + OUT_DIM);
    semantic_weights_kernel<<<1, 256>>>(COLSUM, in_f[L_Q1], OUT_DIM, 1.f / NN, W2);
    combine2_kernel<<<(int)(((long long)NN * OUT_DIM / 4 + TPB - 1) / TPB), TPB>>>(
        AGG1a, AGG1c, W2, R1P, (long long)NN * OUT_DIM / 4);

    // ======== outputs: l2norm(paper), l2norm(relu(author_agg)) ========
    float* out = (float*)d_out;
    int l2Blocks = (NN + 7) / 8;
    l2norm_kernel<<<l2Blocks, TPB>>>(R1P, out, NN, 0);
    l2norm_kernel<<<l2Blocks, TPB>>>(AGG1b, out + (size_t)NN * OUT_DIM, NN, 1);
}

// round 3
// speedup vs baseline: 3.3027x; 1.0264x over previous
#include <cuda_runtime.h>
#include <math.h>
#include <stdint.h>

#define NN 50000
#define EE 300000
#define IN_DIM 768
#define HID 256
#define OUT_DIM 128
#define HEADS 8

// ---------------- scratch (static device globals; no allocation) ----------------
__device__ float g_H0P[NN * HID];
__device__ float g_H0A[NN * HID];
__device__ float g_SC[6][NN * HEADS];   // per-relation src/dst scores
__device__ float g_DEN[NN * HEADS];
__device__ float g_EX[EE * HEADS];      // per-edge-head exp / alpha
__device__ float g_AGG0a[NN * HID];     // writes      -> paper
__device__ float g_AGG0b[NN * HID];     // written_by  -> author
__device__ float g_AGG0c[NN * HID];     // cites       -> paper
__device__ float g_R0P[NN * HID];
__device__ float g_H1P[NN * OUT_DIM];
__device__ float g_H1A[NN * OUT_DIM];
__device__ float g_AGG1a[NN * OUT_DIM];
__device__ float g_AGG1b[NN * OUT_DIM];
__device__ float g_AGG1c[NN * OUT_DIM];
__device__ float g_R1P[NN * OUT_DIM];
__device__ float g_COLSUM[2 * HID];
__device__ float g_W2[2];

// ---------------- TF32 tensor-core GEMM ----------------
__device__ __forceinline__ uint32_t f2tf32(float x) {
    uint32_t r;
    asm("cvt.rna.tf32.f32 %0, %1;" : "=r"(r) : "f"(x));
    return r;
}

__device__ __forceinline__ void mma_tf32(float* d, const uint32_t* a, const uint32_t* b) {
    asm volatile(
        "mma.sync.aligned.m16n8k8.row.col.f32.tf32.tf32.f32 "
        "{%0,%1,%2,%3},{%4,%5,%6,%7},{%8,%9},{%0,%1,%2,%3};"
        : "+f"(d[0]), "+f"(d[1]), "+f"(d[2]), "+f"(d[3])
        : "r"(a[0]), "r"(a[1]), "r"(a[2]), "r"(a[3]), "r"(b[0]), "r"(b[1]));
}

// C[M,N] = A[M,K] @ B[K,N] + bias.
// MODE 0: store. MODE 1: atomically accumulate column sums of tanh(.) into C[N].
// RELU_A: relu applied to A on load. Requires N % 128 == 0, K % 32 == 0.
// Register-prefetch pipeline: global loads for tile t+1 issued before compute of tile t.
template <int MODE, int RELU_A>
__global__ __launch_bounds__(256)
void mma_gemm(int M, int N, int K,
              const float* __restrict__ A, const float* __restrict__ B,
              const float* __restrict__ bias, float* __restrict__ C) {
    __shared__ uint32_t As[128][36];   // pad 4: conflict-free a-frag reads
    __shared__ uint32_t Bs[32][136];   // pad 8: conflict-free b-frag reads

    const int tid = threadIdx.x;
    const int lane = tid & 31;
    const int warp = tid >> 5;
    const int wm = warp & 3;            // 4 warps along M
    const int wn = warp >> 2;           // 2 warps along N
    const int block_row = blockIdx.y * 128;
    const int block_col = blockIdx.x * 128;

    const int arow = tid >> 3, acol = (tid & 7) * 4;
    const int brow = tid >> 5, bcol = (tid & 31) * 4;

    float acc[2][8][4];
#pragma unroll
    for (int mt = 0; mt < 2; mt++)
#pragma unroll
        for (int nt = 0; nt < 8; nt++)
#pragma unroll
            for (int r = 0; r < 4; r++) acc[mt][nt][r] = 0.f;

    float4 aReg[4], bReg[4];
    auto loadG = [&](int k0) {
#pragma unroll
        for (int i = 0; i < 4; i++) {
            int gr = block_row + arow + 32 * i;
            float4 v = make_float4(0.f, 0.f, 0.f, 0.f);
            if (gr < M) v = *(const float4*)(A + (size_t)gr * K + k0 + acol);
            if (RELU_A) {
                v.x = fmaxf(v.x, 0.f); v.y = fmaxf(v.y, 0.f);
                v.z = fmaxf(v.z, 0.f); v.w = fmaxf(v.w, 0.f);
            }
            aReg[i] = v;
        }
#pragma unroll
        for (int i = 0; i < 4; i++)
            bReg[i] = *(const float4*)(B + (size_t)(k0 + brow + 8 * i) * N + block_col + bcol);
    };
    auto storeS = [&]() {
#pragma unroll
        for (int i = 0; i < 4; i++) {
            int r = arow + 32 * i;
            As[r][acol + 0] = f2tf32(aReg[i].x); As[r][acol + 1] = f2tf32(aReg[i].y);
            As[r][acol + 2] = f2tf32(aReg[i].z); As[r][acol + 3] = f2tf32(aReg[i].w);
        }
#pragma unroll
        for (int i = 0; i < 4; i++) {
            int r = brow + 8 * i;
            Bs[r][bcol + 0] = f2tf32(bReg[i].x); Bs[r][bcol + 1] = f2tf32(bReg[i].y);
            Bs[r][bcol + 2] = f2tf32(bReg[i].z); Bs[r][bcol + 3] = f2tf32(bReg[i].w);
        }
    };

    const int numT = K / 32;
    loadG(0);
    for (int t = 0; t < numT; t++) {
        storeS();
        __syncthreads();
        if (t + 1 < numT) loadG((t + 1) * 32);   // latency hidden behind MMA below
#pragma unroll
        for (int k8 = 0; k8 < 32; k8 += 8) {
            uint32_t af[2][4], bf[8][2];
#pragma unroll
            for (int mt = 0; mt < 2; mt++) {
                int r0 = wm * 32 + mt * 16 + (lane >> 2);
                int c0 = k8 + (lane & 3);
                af[mt][0] = As[r0][c0];
                af[mt][1] = As[r0 + 8][c0];
                af[mt][2] = As[r0][c0 + 4];
                af[mt][3] = As[r0 + 8][c0 + 4];
            }
#pragma unroll
            for (int nt = 0; nt < 8; nt++) {
                int n = wn * 64 + nt * 8 + (lane >> 2);
                bf[nt][0] = Bs[k8 + (lane & 3)][n];
                bf[nt][1] = Bs[k8 + 4 + (lane & 3)][n];
            }
#pragma unroll
            for (int mt = 0; mt < 2; mt++)
#pragma unroll
                for (int nt = 0; nt < 8; nt++) mma_tf32(acc[mt][nt], af[mt], bf[nt]);
        }
        __syncthreads();
    }

    if (MODE == 0) {
#pragma unroll
        for (int mt = 0; mt < 2; mt++) {
            int r0 = block_row + wm * 32 + mt * 16 + (lane >> 2);
#pragma unroll
            for (int nt = 0; nt < 8; nt++) {
                int c0 = block_col + wn * 64 + nt * 8 + 2 * (lane & 3);
                if (r0 < M) {
                    C[(size_t)r0 * N + c0]     = acc[mt][nt][0] + bias[c0];
                    C[(size_t)r0 * N + c0 + 1] = acc[mt][nt][1] + bias[c0 + 1];
                }
                if (r0 + 8 < M) {
                    C[(size_t)(r0 + 8) * N + c0]     = acc[mt][nt][2] + bias[c0];
                    C[(size_t)(r0 + 8) * N + c0 + 1] = acc[mt][nt][3] + bias[c0 + 1];
                }
            }
        }
    } else {
        __shared__ float csum[128];
        if (tid < 128) csum[tid] = 0.f;
        __syncthreads();
#pragma unroll
        for (int nt = 0; nt < 8; nt++) {
            int cl = wn * 64 + nt * 8 + 2 * (lane & 3);
            int cg = block_col + cl;
            float l0 = 0.f, l1 = 0.f;
#pragma unroll
            for (int mt = 0; mt < 2; mt++) {
                int r0 = block_row + wm * 32 + mt * 16 + (lane >> 2);
                if (r0 < M) {
                    l0 += tanhf(acc[mt][nt][0] + bias[cg]);
                    l1 += tanhf(acc[mt][nt][1] + bias[cg + 1]);
                }
                if (r0 + 8 < M) {
                    l0 += tanhf(acc[mt][nt][2] + bias[cg]);
                    l1 += tanhf(acc[mt][nt][3] + bias[cg + 1]);
                }
            }
            atomicAdd(&csum[cl], l0);
            atomicAdd(&csum[cl + 1], l1);
        }
        __syncthreads();
        if (tid < 128) atomicAdd(&C[block_col + tid], csum[tid]);
    }
}

// ---------------- fused per-node attention scores ----------------
template <int C, int HEADS_T>
__global__ void scores_multi(const float* __restrict__ H,
                             const float* __restrict__ a0, const float* __restrict__ a1,
                             const float* __restrict__ a2, const float* __restrict__ a3,
                             float* __restrict__ o0, float* __restrict__ o1,
                             float* __restrict__ o2, float* __restrict__ o3,
                             int nA, int n) {
    int w = (blockIdx.x * blockDim.x + threadIdx.x) >> 5;
    if (w >= n) return;
    int lane = threadIdx.x & 31;
    constexpr int EPL = C / 32;
    constexpr int G = 32 / HEADS_T;

    float h[EPL];
    const float* row = H + (size_t)w * C + lane * EPL;
#pragma unroll
    for (int j = 0; j < EPL; j += 4) {
        float4 v = *(const float4*)(row + j);
        h[j] = v.x; h[j + 1] = v.y; h[j + 2] = v.z; h[j + 3] = v.w;
    }
    const float* av[4] = {a0, a1, a2, a3};
    float* ov[4] = {o0, o1, o2, o3};
#pragma unroll
    for (int k = 0; k < 4; k++) {
        if (k >= nA) break;
        const float* a = av[k] + lane * EPL;
        float s = 0.f;
#pragma unroll
        for (int j = 0; j < EPL; j += 4) {
            float4 v = *(const float4*)(a + j);
            s += h[j] * v.x + h[j + 1] * v.y + h[j + 2] * v.z + h[j + 3] * v.w;
        }
#pragma unroll
        for (int off = 1; off < G; off <<= 1) s += __shfl_xor_sync(0xffffffffu, s, off);
        if ((lane & (G - 1)) == 0) ov[k][w * HEADS_T + lane / G] = s;
    }
}

// ---------------- edge kernels ----------------
__device__ __forceinline__ float lrelu02(float x) { return x >= 0.f ? x : 0.2f * x; }

// pass A: ex = exp(lrelu(ss+sd)); den[d,h] += ex
template <int HEADS_T>
__global__ void edge_exp_kernel(const int* __restrict__ ei,
                                const float* __restrict__ ss, const float* __restrict__ sd,
                                float* __restrict__ ex, float* __restrict__ den, int E) {
    int idx = blockIdx.x * blockDim.x + threadIdx.x;
    if (idx >= E * HEADS_T) return;
    int e = idx / HEADS_T, h = idx - e * HEADS_T;
    int s = __ldg(&ei[e]), d = __ldg(&ei[E + e]);
    float al = lrelu02(ss[s * HEADS_T + h] + sd[d * HEADS_T + h]);
    float v = expf(fminf(al, 80.f));
    ex[idx] = v;
    atomicAdd(&den[d * HEADS_T + h], v);
}

// pass B: ex /= den  (in place -> alpha)
template <int HEADS_T>
__global__ void edge_norm_kernel(const int* __restrict__ ei,
                                 float* __restrict__ ex, const float* __restrict__ den, int E) {
    int idx = blockIdx.x * blockDim.x + threadIdx.x;
    if (idx >= E * HEADS_T) return;
    int e = idx / HEADS_T, h = idx - e * HEADS_T;
    int d = __ldg(&ei[E + e]);
    ex[idx] = ex[idx] / (den[d * HEADS_T + h] + 1e-16f);
}

__device__ __forceinline__ void red_add_v4(float* p, float4 v) {
    asm volatile("red.global.add.v4.f32 [%0], {%1,%2,%3,%4};"
                 :: "l"(p), "f"(v.x), "f"(v.y), "f"(v.z), "f"(v.w) : "memory");
}

// pass C: agg[d, :] += alpha * Hsrc[s, :]   (pure memory + red)
template <int C, int HEADS_T>
__global__ void edge_scatter_kernel(const int* __restrict__ ei,
                                    const float* __restrict__ alpha,
                                    const float* __restrict__ Hsrc, float* __restrict__ agg,
                                    int E) {
    constexpr int C4 = C / 4;
    constexpr int D4 = (C / HEADS_T) / 4;   // v4 chunks per head
    long long idx = (long long)blockIdx.x * blockDim.x + threadIdx.x;
    if (idx >= (long long)E * C4) return;
    int e = (int)(idx / C4);
    int c4 = (int)(idx - (long long)e * C4);
    int h = c4 / D4;
    int s = __ldg(&ei[e]), d = __ldg(&ei[E + e]);
    float a = __ldg(&alpha[e * HEADS_T + h]);
    float4 v = *(const float4*)(Hsrc + (size_t)s * C + c4 * 4);
    v.x *= a; v.y *= a; v.z *= a; v.w *= a;
    red_add_v4(agg + (size_t)d * C + c4 * 4, v);
}

// ---------------- small kernels ----------------
__global__ void semantic_weights_kernel(const float* __restrict__ colsum,
                                        const float* __restrict__ q,
                                        int C, float invn, float* __restrict__ w) {
    __shared__ float sh0[256], sh1[256];
    int t = threadIdx.x;
    float s0 = 0.f, s1 = 0.f;
    for (int c = t; c < C; c += blockDim.x) {
        float qc = q[c];
        s0 += qc * colsum[c];
        s1 += qc * colsum[C + c];
    }
    sh0[t] = s0; sh1[t] = s1;
    __syncthreads();
    for (int o = blockDim.x / 2; o > 0; o >>= 1) {
        if (t < o) { sh0[t] += sh0[t + o]; sh1[t] += sh1[t + o]; }
        __syncthreads();
    }
    if (t == 0) {
        float a = sh0[0] * invn, b = sh1[0] * invn;
        float m = fmaxf(a, b);
        float ea = expf(a - m), eb = expf(b - m);
        float inv = 1.f / (ea + eb);
        w[0] = ea * inv; w[1] = eb * inv;
    }
}

__global__ void combine2_kernel(const float* __restrict__ A, const float* __restrict__ B,
                                const float* __restrict__ w, float* __restrict__ out,
                                long long n4) {
    long long i = (long long)blockIdx.x * blockDim.x + threadIdx.x;
    if (i >= n4) return;
    float w0 = w[0], w1 = w[1];
    float4 a = ((const float4*)A)[i];
    float4 b = ((const float4*)B)[i];
    float4 r;
    r.x = w0 * fmaxf(a.x, 0.f) + w1 * fmaxf(b.x, 0.f);
    r.y = w0 * fmaxf(a.y, 0.f) + w1 * fmaxf(b.y, 0.f);
    r.z = w0 * fmaxf(a.z, 0.f) + w1 * fmaxf(b.z, 0.f);
    r.w = w0 * fmaxf(a.w, 0.f) + w1 * fmaxf(b.w, 0.f);
    ((float4*)out)[i] = r;
}

__global__ void l2norm_kernel(const float* __restrict__ in, float* __restrict__ out,
                              int n, int relu) {
    int w = (blockIdx.x * blockDim.x + threadIdx.x) >> 5;
    if (w >= n) return;
    int lane = threadIdx.x & 31;
    float4 v = *(const float4*)(in + (size_t)w * 128 + lane * 4);
    if (relu) {
        v.x = fmaxf(v.x, 0.f); v.y = fmaxf(v.y, 0.f);
        v.z = fmaxf(v.z, 0.f); v.w = fmaxf(v.w, 0.f);
    }
    float s = v.x * v.x + v.y * v.y + v.z * v.z + v.w * v.w;
#pragma unroll
    for (int off = 16; off > 0; off >>= 1) s += __shfl_xor_sync(0xffffffffu, s, off);
    float inv = 1.f / fmaxf(sqrtf(s), 1e-12f);
    v.x *= inv; v.y *= inv; v.z *= inv; v.w *= inv;
    *(float4*)(out + (size_t)w * 128 + lane * 4) = v;
}

// ---------------- host orchestration ----------------
enum {
    L_XP, L_XA, L_W0P, L_B0P, L_W0A, L_B0A,
    L_A0S_W, L_A0D_W, L_A0S_WB, L_A0D_WB, L_A0S_C, L_A0D_C,
    L_WK0, L_BK0, L_Q0,
    L_W1P, L_B1P, L_W1A, L_B1A,
    L_A1S_W, L_A1D_W, L_A1S_WB, L_A1D_WB, L_A1S_C, L_A1D_C,
    L_WK1, L_BK1, L_Q1, L_EIW, L_EIWB, L_EIC, L_COUNT
};

extern "C" void kernel_launch(void* const* d_in, const int* in_sizes, int n_in,
                              void* d_out, int out_size) {
    static const int mapSig[L_COUNT] = {
        0, 1, 2, 3, 4, 5, 6, 7, 8, 9, 10, 11, 12, 13, 14,
        15, 16, 17, 18, 19, 20, 21, 22, 23, 24, 25, 26, 27, 28, 29, 30};
    static const int mapDict[L_COUNT] = {
        0, 1, 5, 6, 7, 8, 9, 10, 11, 12, 13, 14, 15, 16, 17,
        18, 19, 20, 21, 22, 23, 24, 25, 26, 27, 28, 29, 30, 2, 3, 4};
    const int* mp = (n_in > 2 && in_sizes[2] == 2 * EE) ? mapDict : mapSig;

    const float* in_f[L_COUNT];
    for (int i = 0; i < L_COUNT; i++) in_f[i] = (const float*)d_in[mp[i]];
    const int* eiW  = (const int*)d_in[mp[L_EIW]];
    const int* eiWB = (const int*)d_in[mp[L_EIWB]];
    const int* eiC  = (const int*)d_in[mp[L_EIC]];

    float *H0P, *H0A, *SC, *DEN, *EX;
    float *AGG0a, *AGG0b, *AGG0c, *R0P;
    float *H1P, *H1A, *AGG1a, *AGG1b, *AGG1c, *R1P, *COLSUM, *W2;
    cudaGetSymbolAddress((void**)&H0P, g_H0P);
    cudaGetSymbolAddress((void**)&H0A, g_H0A);
    cudaGetSymbolAddress((void**)&SC, g_SC);
    cudaGetSymbolAddress((void**)&DEN, g_DEN);
    cudaGetSymbolAddress((void**)&EX, g_EX);
    cudaGetSymbolAddress((void**)&AGG0a, g_AGG0a);
    cudaGetSymbolAddress((void**)&AGG0b, g_AGG0b);
    cudaGetSymbolAddress((void**)&AGG0c, g_AGG0c);
    cudaGetSymbolAddress((void**)&R0P, g_R0P);
    cudaGetSymbolAddress((void**)&H1P, g_H1P);
    cudaGetSymbolAddress((void**)&H1A, g_H1A);
    cudaGetSymbolAddress((void**)&AGG1a, g_AGG1a);
    cudaGetSymbolAddress((void**)&AGG1b, g_AGG1b);
    cudaGetSymbolAddress((void**)&AGG1c, g_AGG1c);
    cudaGetSymbolAddress((void**)&R1P, g_R1P);
    cudaGetSymbolAddress((void**)&COLSUM, g_COLSUM);
    cudaGetSymbolAddress((void**)&W2, g_W2);

    float* S0 = SC + 0 * (NN * HEADS);
    float* S1 = SC + 1 * (NN * HEADS);
    float* S2 = SC + 2 * (NN * HEADS);
    float* S3 = SC + 3 * (NN * HEADS);
    float* S4 = SC + 4 * (NN * HEADS);
    float* S5 = SC + 5 * (NN * HEADS);

    const int TPB = 256;
    dim3 gGemm256(2, (NN + 127) / 128);
    dim3 gGemm128(1, (NN + 127) / 128);
    int scoreBlocks = (NN + 7) / 8;

    // ======== Layer 0 ========
    mma_gemm<0, 0><<<gGemm256, TPB>>>(NN, HID, IN_DIM, in_f[L_XP], in_f[L_W0P], in_f[L_B0P], H0P);
    mma_gemm<0, 0><<<gGemm256, TPB>>>(NN, HID, IN_DIM, in_f[L_XA], in_f[L_W0A], in_f[L_B0A], H0A);

    scores_multi<HID, HEADS><<<scoreBlocks, TPB>>>(H0P,
        in_f[L_A0D_W], in_f[L_A0S_WB], in_f[L_A0S_C], in_f[L_A0D_C],
        S1, S2, S4, S5, 4, NN);
    scores_multi<HID, HEADS><<<scoreBlocks, TPB>>>(H0A,
        in_f[L_A0S_W], in_f[L_A0D_WB], in_f[L_A0S_W], in_f[L_A0S_W],
        S0, S3, S0, S0, 2, NN);

    auto run_rel0 = [&](const int* ei, const float* Hsrc, const float* ss, const float* sd,
                        float* agg) {
        cudaMemsetAsync(DEN, 0, (size_t)NN * HEADS * sizeof(float));
        int nb = (EE * HEADS + TPB - 1) / TPB;
        edge_exp_kernel<HEADS><<<nb, TPB>>>(ei, ss, sd, EX, DEN, EE);
        edge_norm_kernel<HEADS><<<nb, TPB>>>(ei, EX, DEN, EE);
        cudaMemsetAsync(agg, 0, (size_t)NN * HID * sizeof(float));
        long long tot = (long long)EE * (HID / 4);
        edge_scatter_kernel<HID, HEADS><<<(int)((tot + TPB - 1) / TPB), TPB>>>(
            ei, EX, Hsrc, agg, EE);
    };
    run_rel0(eiW,  H0A, S0, S1, AGG0a);
    run_rel0(eiWB, H0P, S2, S3, AGG0b);
    run_rel0(eiC,  H0P, S4, S5, AGG0c);

    cudaMemsetAsync(COLSUM, 0, 2 * HID * sizeof(float));
    mma_gemm<1, 1><<<gGemm256, TPB>>>(NN, HID, HID, AGG0a, in_f[L_WK0], in_f[L_BK0], COLSUM);
    mma_gemm<1, 1><<<gGemm256, TPB>>>(NN, HID, HID, AGG0c, in_f[L_WK0], in_f[L_BK0], COLSUM + HID);
    semantic_weights_kernel<<<1, 256>>>(COLSUM, in_f[L_Q0], HID, 1.f / NN, W2);
    combine2_kernel<<<(int)(((long long)NN * HID / 4 + TPB - 1) / TPB), TPB>>>(
        AGG0a, AGG0c, W2, R0P, (long long)NN * HID / 4);

    // ======== Layer 1 ========
    mma_gemm<0, 0><<<gGemm128, TPB>>>(NN, OUT_DIM, HID, R0P, in_f[L_W1P], in_f[L_B1P], H1P);
    mma_gemm<0, 1><<<gGemm128, TPB>>>(NN, OUT_DIM, HID, AGG0b, in_f[L_W1A], in_f[L_B1A], H1A);

    scores_multi<OUT_DIM, 1><<<scoreBlocks, TPB>>>(H1P,
        in_f[L_A1D_W], in_f[L_A1S_WB], in_f[L_A1S_C], in_f[L_A1D_C],
        S1, S2, S4, S5, 4, NN);
    scores_multi<OUT_DIM, 1><<<scoreBlocks, TPB>>>(H1A,
        in_f[L_A1S_W], in_f[L_A1D_WB], in_f[L_A1S_W], in_f[L_A1S_W],
        S0, S3, S0, S0, 2, NN);

    auto run_rel1 = [&](const int* ei, const float* Hsrc, const float* ss, const float* sd,
                        float* agg) {
        cudaMemsetAsync(DEN, 0, (size_t)NN * sizeof(float));
        int nb = (EE + TPB - 1) / TPB;
        edge_exp_kernel<1><<<nb, TPB>>>(ei, ss, sd, EX, DEN, EE);
        edge_norm_kernel<1><<<nb, TPB>>>(ei, EX, DEN, EE);
        cudaMemsetAsync(agg, 0, (size_t)NN * OUT_DIM * sizeof(float));
        long long tot = (long long)EE * (OUT_DIM / 4);
        edge_scatter_kernel<OUT_DIM, 1><<<(int)((tot + TPB - 1) / TPB), TPB>>>(
            ei, EX, Hsrc, agg, EE);
    };
    run_rel1(eiW,  H1A, S0, S1, AGG1a);
    run_rel1(eiWB, H1P, S2, S3, AGG1b);
    run_rel1(eiC,  H1P, S4, S5, AGG1c);

    cudaMemsetAsync(COLSUM, 0, 2 * OUT_DIM * sizeof(float));
    mma_gemm<1, 1><<<gGemm128, TPB>>>(NN, OUT_DIM, OUT_DIM, AGG1a, in_f[L_WK1], in_f[L_BK1], COLSUM);
    mma_gemm<1, 1><<<gGemm128, TPB>>>(NN, OUT_DIM, OUT_DIM, AGG1c, in_f[L_WK1], in_f[L_BK1], COLSUM + OUT_DIM);
    semantic_weights_kernel<<<1, 256>>>(COLSUM, in_f[L_Q1], OUT_DIM, 1.f / NN, W2);
    combine2_kernel<<<(int)(((long long)NN * OUT_DIM / 4 + TPB - 1) / TPB), TPB>>>(
        AGG1a, AGG1c, W2, R1P, (long long)NN * OUT_DIM / 4);

    // ======== outputs ========
    float* out = (float*)d_out;
    int l2Blocks = (NN + 7) / 8;
    l2norm_kernel<<<l2Blocks, TPB>>>(R1P, out, NN, 0);
    l2norm_kernel<<<l2Blocks, TPB>>>(AGG1b, out + (size_t)NN * OUT_DIM, NN, 1);
}

// round 4
// speedup vs baseline: 3.7765x; 1.1435x over previous
#include <cuda_runtime.h>
#include <math.h>
#include <stdint.h>

#define NN 50000
#define EE 300000
#define IN_DIM 768
#define HID 256
#define OUT_DIM 128
#define HEADS 8

#define SCAN_B 512
#define NBLK ((NN + SCAN_B - 1) / SCAN_B)   // 98

// ---------------- scratch (static device globals; no allocation) ----------------
__device__ float g_H0P[NN * HID];
__device__ float g_H0A[NN * HID];
__device__ float g_SC[6][NN * HEADS];
__device__ float g_DEN[NN * HEADS];
__device__ float g_EX[EE * HEADS];
__device__ float g_AGG0a[NN * HID];
__device__ float g_AGG0b[NN * HID];
__device__ float g_AGG0c[NN * HID];
__device__ float g_R0P[NN * HID];
__device__ float g_H1P[NN * OUT_DIM];
__device__ float g_H1A[NN * OUT_DIM];
__device__ float g_AGG1a[NN * OUT_DIM];
__device__ float g_AGG1b[NN * OUT_DIM];
__device__ float g_AGG1c[NN * OUT_DIM];
__device__ float g_R1P[NN * OUT_DIM];
__device__ float g_COLSUM[2 * HID];
__device__ float g_W2[2];
// CSR structures (per relation)
__device__ int g_RP[3][NN + 8];
__device__ int g_PERM[3][EE];
__device__ int g_CNT[NN];
__device__ int g_CUR[NN];
__device__ int g_BSUM[NBLK + 8];

// ---------------- TF32 tensor-core GEMM ----------------
__device__ __forceinline__ uint32_t f2tf32(float x) {
    uint32_t r;
    asm("cvt.rna.tf32.f32 %0, %1;" : "=r"(r) : "f"(x));
    return r;
}

__device__ __forceinline__ void mma_tf32(float* d, const uint32_t* a, const uint32_t* b) {
    asm volatile(
        "mma.sync.aligned.m16n8k8.row.col.f32.tf32.tf32.f32 "
        "{%0,%1,%2,%3},{%4,%5,%6,%7},{%8,%9},{%0,%1,%2,%3};"
        : "+f"(d[0]), "+f"(d[1]), "+f"(d[2]), "+f"(d[3])
        : "r"(a[0]), "r"(a[1]), "r"(a[2]), "r"(a[3]), "r"(b[0]), "r"(b[1]));
}

template <int MODE, int RELU_A>
__global__ __launch_bounds__(256)
void mma_gemm(int M, int N, int K,
              const float* __restrict__ A, const float* __restrict__ B,
              const float* __restrict__ bias, float* __restrict__ C) {
    __shared__ uint32_t As[128][36];
    __shared__ uint32_t Bs[32][136];

    const int tid = threadIdx.x;
    const int lane = tid & 31;
    const int warp = tid >> 5;
    const int wm = warp & 3;
    const int wn = warp >> 2;
    const int block_row = blockIdx.y * 128;
    const int block_col = blockIdx.x * 128;

    const int arow = tid >> 3, acol = (tid & 7) * 4;
    const int brow = tid >> 5, bcol = (tid & 31) * 4;

    float acc[2][8][4];
#pragma unroll
    for (int mt = 0; mt < 2; mt++)
#pragma unroll
        for (int nt = 0; nt < 8; nt++)
#pragma unroll
            for (int r = 0; r < 4; r++) acc[mt][nt][r] = 0.f;

    float4 aReg[4], bReg[4];
    auto loadG = [&](int k0) {
#pragma unroll
        for (int i = 0; i < 4; i++) {
            int gr = block_row + arow + 32 * i;
            float4 v = make_float4(0.f, 0.f, 0.f, 0.f);
            if (gr < M) v = *(const float4*)(A + (size_t)gr * K + k0 + acol);
            if (RELU_A) {
                v.x = fmaxf(v.x, 0.f); v.y = fmaxf(v.y, 0.f);
                v.z = fmaxf(v.z, 0.f); v.w = fmaxf(v.w, 0.f);
            }
            aReg[i] = v;
        }
#pragma unroll
        for (int i = 0; i < 4; i++)
            bReg[i] = *(const float4*)(B + (size_t)(k0 + brow + 8 * i) * N + block_col + bcol);
    };
    auto storeS = [&]() {
#pragma unroll
        for (int i = 0; i < 4; i++) {
            int r = arow + 32 * i;
            As[r][acol + 0] = f2tf32(aReg[i].x); As[r][acol + 1] = f2tf32(aReg[i].y);
            As[r][acol + 2] = f2tf32(aReg[i].z); As[r][acol + 3] = f2tf32(aReg[i].w);
        }
#pragma unroll
        for (int i = 0; i < 4; i++) {
            int r = brow + 8 * i;
            Bs[r][bcol + 0] = f2tf32(bReg[i].x); Bs[r][bcol + 1] = f2tf32(bReg[i].y);
            Bs[r][bcol + 2] = f2tf32(bReg[i].z); Bs[r][bcol + 3] = f2tf32(bReg[i].w);
        }
    };

    const int numT = K / 32;
    loadG(0);
    for (int t = 0; t < numT; t++) {
        storeS();
        __syncthreads();
        if (t + 1 < numT) loadG((t + 1) * 32);
#pragma unroll
        for (int k8 = 0; k8 < 32; k8 += 8) {
            uint32_t af[2][4], bf[8][2];
#pragma unroll
            for (int mt = 0; mt < 2; mt++) {
                int r0 = wm * 32 + mt * 16 + (lane >> 2);
                int c0 = k8 + (lane & 3);
                af[mt][0] = As[r0][c0];
                af[mt][1] = As[r0 + 8][c0];
                af[mt][2] = As[r0][c0 + 4];
                af[mt][3] = As[r0 + 8][c0 + 4];
            }
#pragma unroll
            for (int nt = 0; nt < 8; nt++) {
                int n = wn * 64 + nt * 8 + (lane >> 2);
                bf[nt][0] = Bs[k8 + (lane & 3)][n];
                bf[nt][1] = Bs[k8 + 4 + (lane & 3)][n];
            }
#pragma unroll
            for (int mt = 0; mt < 2; mt++)
#pragma unroll
                for (int nt = 0; nt < 8; nt++) mma_tf32(acc[mt][nt], af[mt], bf[nt]);
        }
        __syncthreads();
    }

    if (MODE == 0) {
#pragma unroll
        for (int mt = 0; mt < 2; mt++) {
            int r0 = block_row + wm * 32 + mt * 16 + (lane >> 2);
#pragma unroll
            for (int nt = 0; nt < 8; nt++) {
                int c0 = block_col + wn * 64 + nt * 8 + 2 * (lane & 3);
                if (r0 < M) {
                    C[(size_t)r0 * N + c0]     = acc[mt][nt][0] + bias[c0];
                    C[(size_t)r0 * N + c0 + 1] = acc[mt][nt][1] + bias[c0 + 1];
                }
                if (r0 + 8 < M) {
                    C[(size_t)(r0 + 8) * N + c0]     = acc[mt][nt][2] + bias[c0];
                    C[(size_t)(r0 + 8) * N + c0 + 1] = acc[mt][nt][3] + bias[c0 + 1];
                }
            }
        }
    } else {
        __shared__ float csum[128];
        if (tid < 128) csum[tid] = 0.f;
        __syncthreads();
#pragma unroll
        for (int nt = 0; nt < 8; nt++) {
            int cl = wn * 64 + nt * 8 + 2 * (lane & 3);
            int cg = block_col + cl;
            float l0 = 0.f, l1 = 0.f;
#pragma unroll
            for (int mt = 0; mt < 2; mt++) {
                int r0 = block_row + wm * 32 + mt * 16 + (lane >> 2);
                if (r0 < M) {
                    l0 += tanhf(acc[mt][nt][0] + bias[cg]);
                    l1 += tanhf(acc[mt][nt][1] + bias[cg + 1]);
                }
                if (r0 + 8 < M) {
                    l0 += tanhf(acc[mt][nt][2] + bias[cg]);
                    l1 += tanhf(acc[mt][nt][3] + bias[cg + 1]);
                }
            }
            atomicAdd(&csum[cl], l0);
            atomicAdd(&csum[cl + 1], l1);
        }
        __syncthreads();
        if (tid < 128) atomicAdd(&C[block_col + tid], csum[tid]);
    }
}

// ---------------- CSR build ----------------
__global__ void hist_kernel(const int* __restrict__ ei, int* __restrict__ cnt, int E) {
    int i = blockIdx.x * blockDim.x + threadIdx.x;
    if (i < E) atomicAdd(&cnt[ei[E + i]], 1);
}

__global__ void scanA_kernel(const int* __restrict__ cnt, int* __restrict__ rp,
                             int* __restrict__ bsum) {
    __shared__ int sh[SCAN_B];
    int t = threadIdx.x;
    int i = blockIdx.x * SCAN_B + t;
    int v = (i < NN) ? cnt[i] : 0;
    sh[t] = v;
    __syncthreads();
    for (int off = 1; off < SCAN_B; off <<= 1) {
        int x = (t >= off) ? sh[t - off] : 0;
        __syncthreads();
        sh[t] += x;
        __syncthreads();
    }
    if (i < NN) rp[i] = sh[t] - v;   // local exclusive
    if (t == SCAN_B - 1) bsum[blockIdx.x] = sh[t];
}

__global__ void scanB_kernel(int* __restrict__ bsum, int nb) {
    if (threadIdx.x == 0 && blockIdx.x == 0) {
        int run = 0;
        for (int b = 0; b < nb; b++) { int x = bsum[b]; bsum[b] = run; run += x; }
    }
}

__global__ void scanC_kernel(int* __restrict__ rp, const int* __restrict__ bsum,
                             int* __restrict__ cur, int E) {
    int i = blockIdx.x * blockDim.x + threadIdx.x;
    if (i < NN) {
        int v = rp[i] + bsum[i / SCAN_B];
        rp[i] = v;
        cur[i] = v;
    }
    if (i == 0) rp[NN] = E;
}

__global__ void fill_kernel(const int* __restrict__ ei, int* __restrict__ cur,
                            int* __restrict__ perm, int E) {
    int i = blockIdx.x * blockDim.x + threadIdx.x;
    if (i < E) {
        int d = ei[E + i];
        int pos = atomicAdd(&cur[d], 1);
        perm[pos] = i;
    }
}

// ---------------- fused per-node attention scores ----------------
template <int C, int HEADS_T>
__global__ void scores_multi(const float* __restrict__ H,
                             const float* __restrict__ a0, const float* __restrict__ a1,
                             const float* __restrict__ a2, const float* __restrict__ a3,
                             float* __restrict__ o0, float* __restrict__ o1,
                             float* __restrict__ o2, float* __restrict__ o3,
                             int nA, int n) {
    int w = (blockIdx.x * blockDim.x + threadIdx.x) >> 5;
    if (w >= n) return;
    int lane = threadIdx.x & 31;
    constexpr int EPL = C / 32;
    constexpr int G = 32 / HEADS_T;

    float h[EPL];
    const float* row = H + (size_t)w * C + lane * EPL;
#pragma unroll
    for (int j = 0; j < EPL; j += 4) {
        float4 v = *(const float4*)(row + j);
        h[j] = v.x; h[j + 1] = v.y; h[j + 2] = v.z; h[j + 3] = v.w;
    }
    const float* av[4] = {a0, a1, a2, a3};
    float* ov[4] = {o0, o1, o2, o3};
#pragma unroll
    for (int k = 0; k < 4; k++) {
        if (k >= nA) break;
        const float* a = av[k] + lane * EPL;
        float s = 0.f;
#pragma unroll
        for (int j = 0; j < EPL; j += 4) {
            float4 v = *(const float4*)(a + j);
            s += h[j] * v.x + h[j + 1] * v.y + h[j + 2] * v.z + h[j + 3] * v.w;
        }
#pragma unroll
        for (int off = 1; off < G; off <<= 1) s += __shfl_xor_sync(0xffffffffu, s, off);
        if ((lane & (G - 1)) == 0) ov[k][w * HEADS_T + lane / G] = s;
    }
}

// ---------------- edge kernels ----------------
__device__ __forceinline__ float lrelu02(float x) { return x >= 0.f ? x : 0.2f * x; }

// ex = exp(lrelu(ss+sd)); den[d,h] += ex
template <int HEADS_T>
__global__ void edge_exp_kernel(const int* __restrict__ ei,
                                const float* __restrict__ ss, const float* __restrict__ sd,
                                float* __restrict__ ex, float* __restrict__ den, int E) {
    int idx = blockIdx.x * blockDim.x + threadIdx.x;
    if (idx >= E * HEADS_T) return;
    int e = idx / HEADS_T, h = idx - e * HEADS_T;
    int s = __ldg(&ei[e]), d = __ldg(&ei[E + e]);
    float al = lrelu02(ss[s * HEADS_T + h] + sd[d * HEADS_T + h]);
    float v = expf(fminf(al, 80.f));
    ex[idx] = v;
    atomicAdd(&den[d * HEADS_T + h], v);
}

// CSR gather: warp per dst node; registers accumulate C channels; relu on store.
template <int C, int HEADS_T>
__global__ void csr_gather_kernel(const int* __restrict__ ei,
                                  const int* __restrict__ rp, const int* __restrict__ perm,
                                  const float* __restrict__ ex, const float* __restrict__ den,
                                  const float* __restrict__ Hsrc, float* __restrict__ agg,
                                  int E) {
    int w = (blockIdx.x * blockDim.x + threadIdx.x) >> 5;
    if (w >= NN) return;
    int lane = threadIdx.x & 31;
    constexpr int EPL = C / 32;                      // 8 (l0) or 4 (l1)
    int h = (HEADS_T == 1) ? 0 : (lane >> 2);        // head per lane (C=256,H=8: lane/4)
    float inv_den = 1.f / (den[w * HEADS_T + h] + 1e-16f);

    float acc[EPL];
#pragma unroll
    for (int j = 0; j < EPL; j++) acc[j] = 0.f;

    int beg = rp[w], end = rp[w + 1];
    const float* base = Hsrc + (size_t)lane * EPL;
    for (int p = beg; p < end; p++) {
        int e = __ldg(&perm[p]);
        int s = __ldg(&ei[e]);
        float a = __ldg(&ex[e * HEADS_T + h]) * inv_den;
        const float* src = base + (size_t)s * C;
#pragma unroll
        for (int j = 0; j < EPL; j += 4) {
            float4 v = *(const float4*)(src + j);
            acc[j]     += a * v.x;
            acc[j + 1] += a * v.y;
            acc[j + 2] += a * v.z;
            acc[j + 3] += a * v.w;
        }
    }
    float* dst = agg + (size_t)w * C + lane * EPL;
#pragma unroll
    for (int j = 0; j < EPL; j += 4) {
        float4 v;
        v.x = fmaxf(acc[j], 0.f);
        v.y = fmaxf(acc[j + 1], 0.f);
        v.z = fmaxf(acc[j + 2], 0.f);
        v.w = fmaxf(acc[j + 3], 0.f);
        *(float4*)(dst + j) = v;
    }
}

// ---------------- small kernels ----------------
__global__ void semantic_weights_kernel(const float* __restrict__ colsum,
                                        const float* __restrict__ q,
                                        int C, float invn, float* __restrict__ w) {
    __shared__ float sh0[256], sh1[256];
    int t = threadIdx.x;
    float s0 = 0.f, s1 = 0.f;
    for (int c = t; c < C; c += blockDim.x) {
        float qc = q[c];
        s0 += qc * colsum[c];
        s1 += qc * colsum[C + c];
    }
    sh0[t] = s0; sh1[t] = s1;
    __syncthreads();
    for (int o = blockDim.x / 2; o > 0; o >>= 1) {
        if (t < o) { sh0[t] += sh0[t + o]; sh1[t] += sh1[t + o]; }
        __syncthreads();
    }
    if (t == 0) {
        float a = sh0[0] * invn, b = sh1[0] * invn;
        float m = fmaxf(a, b);
        float ea = expf(a - m), eb = expf(b - m);
        float inv = 1.f / (ea + eb);
        w[0] = ea * inv; w[1] = eb * inv;
    }
}

__global__ void combine2_kernel(const float* __restrict__ A, const float* __restrict__ B,
                                const float* __restrict__ w, float* __restrict__ out,
                                long long n4) {
    long long i = (long long)blockIdx.x * blockDim.x + threadIdx.x;
    if (i >= n4) return;
    float w0 = w[0], w1 = w[1];
    float4 a = ((const float4*)A)[i];
    float4 b = ((const float4*)B)[i];
    float4 r;
    r.x = w0 * a.x + w1 * b.x;
    r.y = w0 * a.y + w1 * b.y;
    r.z = w0 * a.z + w1 * b.z;
    r.w = w0 * a.w + w1 * b.w;
    ((float4*)out)[i] = r;
}

__global__ void l2norm_kernel(const float* __restrict__ in, float* __restrict__ out, int n) {
    int w = (blockIdx.x * blockDim.x + threadIdx.x) >> 5;
    if (w >= n) return;
    int lane = threadIdx.x & 31;
    float4 v = *(const float4*)(in + (size_t)w * 128 + lane * 4);
    float s = v.x * v.x + v.y * v.y + v.z * v.z + v.w * v.w;
#pragma unroll
    for (int off = 16; off > 0; off >>= 1) s += __shfl_xor_sync(0xffffffffu, s, off);
    float inv = 1.f / fmaxf(sqrtf(s), 1e-12f);
    v.x *= inv; v.y *= inv; v.z *= inv; v.w *= inv;
    *(float4*)(out + (size_t)w * 128 + lane * 4) = v;
}

// ---------------- host orchestration ----------------
enum {
    L_XP, L_XA, L_W0P, L_B0P, L_W0A, L_B0A,
    L_A0S_W, L_A0D_W, L_A0S_WB, L_A0D_WB, L_A0S_C, L_A0D_C,
    L_WK0, L_BK0, L_Q0,
    L_W1P, L_B1P, L_W1A, L_B1A,
    L_A1S_W, L_A1D_W, L_A1S_WB, L_A1D_WB, L_A1S_C, L_A1D_C,
    L_WK1, L_BK1, L_Q1, L_EIW, L_EIWB, L_EIC, L_COUNT
};

extern "C" void kernel_launch(void* const* d_in, const int* in_sizes, int n_in,
                              void* d_out, int out_size) {
    static const int mapSig[L_COUNT] = {
        0, 1, 2, 3, 4, 5, 6, 7, 8, 9, 10, 11, 12, 13, 14,
        15, 16, 17, 18, 19, 20, 21, 22, 23, 24, 25, 26, 27, 28, 29, 30};
    static const int mapDict[L_COUNT] = {
        0, 1, 5, 6, 7, 8, 9, 10, 11, 12, 13, 14, 15, 16, 17,
        18, 19, 20, 21, 22, 23, 24, 25, 26, 27, 28, 29, 30, 2, 3, 4};
    const int* mp = (n_in > 2 && in_sizes[2] == 2 * EE) ? mapDict : mapSig;

    const float* in_f[L_COUNT];
    for (int i = 0; i < L_COUNT; i++) in_f[i] = (const float*)d_in[mp[i]];
    const int* ei[3] = {(const int*)d_in[mp[L_EIW]],
                        (const int*)d_in[mp[L_EIWB]],
                        (const int*)d_in[mp[L_EIC]]};

    float *H0P, *H0A, *SC, *DEN, *EX;
    float *AGG0a, *AGG0b, *AGG0c, *R0P;
    float *H1P, *H1A, *AGG1a, *AGG1b, *AGG1c, *R1P, *COLSUM, *W2;
    int *RP, *PERM, *CNT, *CUR, *BSUM;
    cudaGetSymbolAddress((void**)&H0P, g_H0P);
    cudaGetSymbolAddress((void**)&H0A, g_H0A);
    cudaGetSymbolAddress((void**)&SC, g_SC);
    cudaGetSymbolAddress((void**)&DEN, g_DEN);
    cudaGetSymbolAddress((void**)&EX, g_EX);
    cudaGetSymbolAddress((void**)&AGG0a, g_AGG0a);
    cudaGetSymbolAddress((void**)&AGG0b, g_AGG0b);
    cudaGetSymbolAddress((void**)&AGG0c, g_AGG0c);
    cudaGetSymbolAddress((void**)&R0P, g_R0P);
    cudaGetSymbolAddress((void**)&H1P, g_H1P);
    cudaGetSymbolAddress((void**)&H1A, g_H1A);
    cudaGetSymbolAddress((void**)&AGG1a, g_AGG1a);
    cudaGetSymbolAddress((void**)&AGG1b, g_AGG1b);
    cudaGetSymbolAddress((void**)&AGG1c, g_AGG1c);
    cudaGetSymbolAddress((void**)&R1P, g_R1P);
    cudaGetSymbolAddress((void**)&COLSUM, g_COLSUM);
    cudaGetSymbolAddress((void**)&W2, g_W2);
    cudaGetSymbolAddress((void**)&RP, g_RP);
    cudaGetSymbolAddress((void**)&PERM, g_PERM);
    cudaGetSymbolAddress((void**)&CNT, g_CNT);
    cudaGetSymbolAddress((void**)&CUR, g_CUR);
    cudaGetSymbolAddress((void**)&BSUM, g_BSUM);

    float* S0 = SC + 0 * (NN * HEADS);
    float* S1 = SC + 1 * (NN * HEADS);
    float* S2 = SC + 2 * (NN * HEADS);
    float* S3 = SC + 3 * (NN * HEADS);
    float* S4 = SC + 4 * (NN * HEADS);
    float* S5 = SC + 5 * (NN * HEADS);

    const int TPB = 256;
    dim3 gGemm256(2, (NN + 127) / 128);
    dim3 gGemm128(1, (NN + 127) / 128);
    int warpBlocks = (NN * 32 + TPB - 1) / TPB;   // warp-per-node kernels
    int scoreBlocks = (NN + 7) / 8;

    // ======== CSR builds (edges shared by both layers) ========
    for (int r = 0; r < 3; r++) {
        int* rp = RP + r * (NN + 8);
        int* perm = PERM + r * EE;
        cudaMemsetAsync(CNT, 0, NN * sizeof(int));
        hist_kernel<<<(EE + TPB - 1) / TPB, TPB>>>(ei[r], CNT, EE);
        scanA_kernel<<<NBLK, SCAN_B>>>(CNT, rp, BSUM);
        scanB_kernel<<<1, 32>>>(BSUM, NBLK);
        scanC_kernel<<<(NN + TPB - 1) / TPB, TPB>>>(rp, BSUM, CUR, EE);
        fill_kernel<<<(EE + TPB - 1) / TPB, TPB>>>(ei[r], CUR, perm, EE);
    }
    int* rpW  = RP + 0 * (NN + 8);  int* pmW  = PERM + 0 * EE;
    int* rpWB = RP + 1 * (NN + 8);  int* pmWB = PERM + 1 * EE;
    int* rpC  = RP + 2 * (NN + 8);  int* pmC  = PERM + 2 * EE;

    // ======== Layer 0 ========
    mma_gemm<0, 0><<<gGemm256, TPB>>>(NN, HID, IN_DIM, in_f[L_XP], in_f[L_W0P], in_f[L_B0P], H0P);
    mma_gemm<0, 0><<<gGemm256, TPB>>>(NN, HID, IN_DIM, in_f[L_XA], in_f[L_W0A], in_f[L_B0A], H0A);

    scores_multi<HID, HEADS><<<scoreBlocks, TPB>>>(H0P,
        in_f[L_A0D_W], in_f[L_A0S_WB], in_f[L_A0S_C], in_f[L_A0D_C],
        S1, S2, S4, S5, 4, NN);
    scores_multi<HID, HEADS><<<scoreBlocks, TPB>>>(H0A,
        in_f[L_A0S_W], in_f[L_A0D_WB], in_f[L_A0S_W], in_f[L_A0S_W],
        S0, S3, S0, S0, 2, NN);

    auto run_rel0 = [&](const int* e, const int* rp, const int* pm, const float* Hsrc,
                        const float* ss, const float* sd, float* agg) {
        cudaMemsetAsync(DEN, 0, (size_t)NN * HEADS * sizeof(float));
        edge_exp_kernel<HEADS><<<(EE * HEADS + TPB - 1) / TPB, TPB>>>(e, ss, sd, EX, DEN, EE);
        csr_gather_kernel<HID, HEADS><<<warpBlocks, TPB>>>(e, rp, pm, EX, DEN, Hsrc, agg, EE);
    };
    run_rel0(ei[0], rpW,  pmW,  H0A, S0, S1, AGG0a);
    run_rel0(ei[1], rpWB, pmWB, H0P, S2, S3, AGG0b);
    run_rel0(ei[2], rpC,  pmC,  H0P, S4, S5, AGG0c);

    cudaMemsetAsync(COLSUM, 0, 2 * HID * sizeof(float));
    mma_gemm<1, 0><<<gGemm256, TPB>>>(NN, HID, HID, AGG0a, in_f[L_WK0], in_f[L_BK0], COLSUM);
    mma_gemm<1, 0><<<gGemm256, TPB>>>(NN, HID, HID, AGG0c, in_f[L_WK0], in_f[L_BK0], COLSUM + HID);
    semantic_weights_kernel<<<1, 256>>>(COLSUM, in_f[L_Q0], HID, 1.f / NN, W2);
    combine2_kernel<<<(int)(((long long)NN * HID / 4 + TPB - 1) / TPB), TPB>>>(
        AGG0a, AGG0c, W2, R0P, (long long)NN * HID / 4);

    // ======== Layer 1 ========
    mma_gemm<0, 0><<<gGemm128, TPB>>>(NN, OUT_DIM, HID, R0P, in_f[L_W1P], in_f[L_B1P], H1P);
    mma_gemm<0, 0><<<gGemm128, TPB>>>(NN, OUT_DIM, HID, AGG0b, in_f[L_W1A], in_f[L_B1A], H1A);

    scores_multi<OUT_DIM, 1><<<scoreBlocks, TPB>>>(H1P,
        in_f[L_A1D_W], in_f[L_A1S_WB], in_f[L_A1S_C], in_f[L_A1D_C],
        S1, S2, S4, S5, 4, NN);
    scores_multi<OUT_DIM, 1><<<scoreBlocks, TPB>>>(H1A,
        in_f[L_A1S_W], in_f[L_A1D_WB], in_f[L_A1S_W], in_f[L_A1S_W],
        S0, S3, S0, S0, 2, NN);

    auto run_rel1 = [&](const int* e, const int* rp, const int* pm, const float* Hsrc,
                        const float* ss, const float* sd, float* agg) {
        cudaMemsetAsync(DEN, 0, (size_t)NN * sizeof(float));
        edge_exp_kernel<1><<<(EE + TPB - 1) / TPB, TPB>>>(e, ss, sd, EX, DEN, EE);
        csr_gather_kernel<OUT_DIM, 1><<<warpBlocks, TPB>>>(e, rp, pm, EX, DEN, Hsrc, agg, EE);
    };
    run_rel1(ei[0], rpW,  pmW,  H1A, S0, S1, AGG1a);
    run_rel1(ei[1], rpWB, pmWB, H1P, S2, S3, AGG1b);
    run_rel1(ei[2], rpC,  pmC,  H1P, S4, S5, AGG1c);

    cudaMemsetAsync(COLSUM, 0, 2 * OUT_DIM * sizeof(float));
    mma_gemm<1, 0><<<gGemm128, TPB>>>(NN, OUT_DIM, OUT_DIM, AGG1a, in_f[L_WK1], in_f[L_BK1], COLSUM);
    mma_gemm<1, 0><<<gGemm128, TPB>>>(NN, OUT_DIM, OUT_DIM, AGG1c, in_f[L_WK1], in_f[L_BK1], COLSUM + OUT_DIM);
    semantic_weights_kernel<<<1, 256>>>(COLSUM, in_f[L_Q1], OUT_DIM, 1.f / NN, W2);
    combine2_kernel<<<(int)(((long long)NN * OUT_DIM / 4 + TPB - 1) / TPB), TPB>>>(
        AGG1a, AGG1c, W2, R1P, (long long)NN * OUT_DIM / 4);

    // ======== outputs ========
    float* out = (float*)d_out;
    int l2Blocks = (NN + 7) / 8;
    l2norm_kernel<<<l2Blocks, TPB>>>(R1P, out, NN);
    l2norm_kernel<<<l2Blocks, TPB>>>(AGG1b, out + (size_t)NN * OUT_DIM, NN);
}

// round 5
// speedup vs baseline: 3.9342x; 1.0417x over previous
#include <cuda_runtime.h>
#include <math.h>
#include <stdint.h>

#define NN 50000
#define EE 300000
#define IN_DIM 768
#define HID 256
#define OUT_DIM 128
#define HEADS 8

#define SCAN_B 512
#define NTOT (3 * NN)
#define NBLK3 ((NTOT + SCAN_B - 1) / SCAN_B)   // 293

// ---------------- scratch (static device globals; no allocation) ----------------
__device__ float g_H0P[NN * HID];
__device__ float g_H0A[NN * HID];
__device__ float g_SC[6][NN * HEADS];
__device__ float g_AGG0a[NN * HID];
__device__ float g_AGG0b[NN * HID];
__device__ float g_AGG0c[NN * HID];
__device__ float g_H1P[NN * OUT_DIM];
__device__ float g_H1A[NN * OUT_DIM];
__device__ float g_AGG1a[NN * OUT_DIM];
__device__ float g_AGG1b[NN * OUT_DIM];
__device__ float g_AGG1c[NN * OUT_DIM];
__device__ float g_COLSUM[2 * HID];
__device__ float g_W2[4];                 // [0..1]=layer0, [2..3]=layer1
// CSR (all 3 relations concatenated)
__device__ int g_RP[NTOT + 8];
__device__ int g_PERM[3 * EE];
__device__ int g_CNT[NTOT];
__device__ int g_CUR[NTOT];
__device__ int g_BSUM[NBLK3 + 8];

// ---------------- TF32 tensor-core GEMM ----------------
__device__ __forceinline__ uint32_t f2tf32(float x) {
    uint32_t r;
    asm("cvt.rna.tf32.f32 %0, %1;" : "=r"(r) : "f"(x));
    return r;
}

__device__ __forceinline__ void mma_tf32(float* d, const uint32_t* a, const uint32_t* b) {
    asm volatile(
        "mma.sync.aligned.m16n8k8.row.col.f32.tf32.tf32.f32 "
        "{%0,%1,%2,%3},{%4,%5,%6,%7},{%8,%9},{%0,%1,%2,%3};"
        : "+f"(d[0]), "+f"(d[1]), "+f"(d[2]), "+f"(d[3])
        : "r"(a[0]), "r"(a[1]), "r"(a[2]), "r"(a[3]), "r"(b[0]), "r"(b[1]));
}

// C[M,N] = A' @ B + bias, A' = A (COMBINE=0) or wv[0]*A + wv[1]*A2 (COMBINE=1).
// MODE 0: store. MODE 1: atomically accumulate tanh(.) column sums into C[N].
template <int MODE, int COMBINE>
__global__ __launch_bounds__(256)
void mma_gemm(int M, int N, int K,
              const float* __restrict__ A, const float* __restrict__ A2,
              const float* __restrict__ B,
              const float* __restrict__ bias, float* __restrict__ C,
              const float* __restrict__ wv) {
    __shared__ uint32_t As[128][36];
    __shared__ uint32_t Bs[32][136];

    const int tid = threadIdx.x;
    const int lane = tid & 31;
    const int warp = tid >> 5;
    const int wm = warp & 3;
    const int wn = warp >> 2;
    const int block_row = blockIdx.y * 128;
    const int block_col = blockIdx.x * 128;

    float w0 = 1.f, w1 = 0.f;
    if (COMBINE) { w0 = wv[0]; w1 = wv[1]; }

    const int arow = tid >> 3, acol = (tid & 7) * 4;
    const int brow = tid >> 5, bcol = (tid & 31) * 4;

    float acc[2][8][4];
#pragma unroll
    for (int mt = 0; mt < 2; mt++)
#pragma unroll
        for (int nt = 0; nt < 8; nt++)
#pragma unroll
            for (int r = 0; r < 4; r++) acc[mt][nt][r] = 0.f;

    float4 aReg[4], bReg[4];
    auto loadG = [&](int k0) {
#pragma unroll
        for (int i = 0; i < 4; i++) {
            int gr = block_row + arow + 32 * i;
            float4 v = make_float4(0.f, 0.f, 0.f, 0.f);
            if (gr < M) {
                v = *(const float4*)(A + (size_t)gr * K + k0 + acol);
                if (COMBINE) {
                    float4 u = *(const float4*)(A2 + (size_t)gr * K + k0 + acol);
                    v.x = w0 * v.x + w1 * u.x; v.y = w0 * v.y + w1 * u.y;
                    v.z = w0 * v.z + w1 * u.z; v.w = w0 * v.w + w1 * u.w;
                }
            }
            aReg[i] = v;
        }
#pragma unroll
        for (int i = 0; i < 4; i++)
            bReg[i] = *(const float4*)(B + (size_t)(k0 + brow + 8 * i) * N + block_col + bcol);
    };
    auto storeS = [&]() {
#pragma unroll
        for (int i = 0; i < 4; i++) {
            int r = arow + 32 * i;
            As[r][acol + 0] = f2tf32(aReg[i].x); As[r][acol + 1] = f2tf32(aReg[i].y);
            As[r][acol + 2] = f2tf32(aReg[i].z); As[r][acol + 3] = f2tf32(aReg[i].w);
        }
#pragma unroll
        for (int i = 0; i < 4; i++) {
            int r = brow + 8 * i;
            Bs[r][bcol + 0] = f2tf32(bReg[i].x); Bs[r][bcol + 1] = f2tf32(bReg[i].y);
            Bs[r][bcol + 2] = f2tf32(bReg[i].z); Bs[r][bcol + 3] = f2tf32(bReg[i].w);
        }
    };

    const int numT = K / 32;
    loadG(0);
    for (int t = 0; t < numT; t++) {
        storeS();
        __syncthreads();
        if (t + 1 < numT) loadG((t + 1) * 32);
#pragma unroll
        for (int k8 = 0; k8 < 32; k8 += 8) {
            uint32_t af[2][4], bf[8][2];
#pragma unroll
            for (int mt = 0; mt < 2; mt++) {
                int r0 = wm * 32 + mt * 16 + (lane >> 2);
                int c0 = k8 + (lane & 3);
                af[mt][0] = As[r0][c0];
                af[mt][1] = As[r0 + 8][c0];
                af[mt][2] = As[r0][c0 + 4];
                af[mt][3] = As[r0 + 8][c0 + 4];
            }
#pragma unroll
            for (int nt = 0; nt < 8; nt++) {
                int n = wn * 64 + nt * 8 + (lane >> 2);
                bf[nt][0] = Bs[k8 + (lane & 3)][n];
                bf[nt][1] = Bs[k8 + 4 + (lane & 3)][n];
            }
#pragma unroll
            for (int mt = 0; mt < 2; mt++)
#pragma unroll
                for (int nt = 0; nt < 8; nt++) mma_tf32(acc[mt][nt], af[mt], bf[nt]);
        }
        __syncthreads();
    }

    if (MODE == 0) {
#pragma unroll
        for (int mt = 0; mt < 2; mt++) {
            int r0 = block_row + wm * 32 + mt * 16 + (lane >> 2);
#pragma unroll
            for (int nt = 0; nt < 8; nt++) {
                int c0 = block_col + wn * 64 + nt * 8 + 2 * (lane & 3);
                if (r0 < M) {
                    C[(size_t)r0 * N + c0]     = acc[mt][nt][0] + bias[c0];
                    C[(size_t)r0 * N + c0 + 1] = acc[mt][nt][1] + bias[c0 + 1];
                }
                if (r0 + 8 < M) {
                    C[(size_t)(r0 + 8) * N + c0]     = acc[mt][nt][2] + bias[c0];
                    C[(size_t)(r0 + 8) * N + c0 + 1] = acc[mt][nt][3] + bias[c0 + 1];
                }
            }
        }
    } else {
        __shared__ float csum[128];
        if (tid < 128) csum[tid] = 0.f;
        __syncthreads();
#pragma unroll
        for (int nt = 0; nt < 8; nt++) {
            int cl = wn * 64 + nt * 8 + 2 * (lane & 3);
            int cg = block_col + cl;
            float l0 = 0.f, l1 = 0.f;
#pragma unroll
            for (int mt = 0; mt < 2; mt++) {
                int r0 = block_row + wm * 32 + mt * 16 + (lane >> 2);
                if (r0 < M) {
                    l0 += tanhf(acc[mt][nt][0] + bias[cg]);
                    l1 += tanhf(acc[mt][nt][1] + bias[cg + 1]);
                }
                if (r0 + 8 < M) {
                    l0 += tanhf(acc[mt][nt][2] + bias[cg]);
                    l1 += tanhf(acc[mt][nt][3] + bias[cg + 1]);
                }
            }
            atomicAdd(&csum[cl], l0);
            atomicAdd(&csum[cl + 1], l1);
        }
        __syncthreads();
        if (tid < 128) atomicAdd(&C[block_col + tid], csum[tid]);
    }
}

// ---------------- unified CSR build (3 relations) ----------------
__global__ void hist3_kernel(const int* __restrict__ e0, const int* __restrict__ e1,
                             const int* __restrict__ e2, int* __restrict__ cnt) {
    int i = blockIdx.x * blockDim.x + threadIdx.x;
    if (i >= 3 * EE) return;
    int r = i / EE, j = i - r * EE;
    const int* e = (r == 0) ? e0 : (r == 1) ? e1 : e2;
    atomicAdd(&cnt[r * NN + e[EE + j]], 1);
}

__global__ void scanA_kernel(const int* __restrict__ cnt, int* __restrict__ rp,
                             int* __restrict__ bsum) {
    __shared__ int sh[SCAN_B];
    int t = threadIdx.x;
    int i = blockIdx.x * SCAN_B + t;
    int v = (i < NTOT) ? cnt[i] : 0;
    sh[t] = v;
    __syncthreads();
    for (int off = 1; off < SCAN_B; off <<= 1) {
        int x = (t >= off) ? sh[t - off] : 0;
        __syncthreads();
        sh[t] += x;
        __syncthreads();
    }
    if (i < NTOT) rp[i] = sh[t] - v;
    if (t == SCAN_B - 1) bsum[blockIdx.x] = sh[t];
}

__global__ void scanB_kernel(int* __restrict__ bsum, int nb) {
    __shared__ int sh[SCAN_B];
    int t = threadIdx.x;
    int v = (t < nb) ? bsum[t] : 0;
    sh[t] = v;
    __syncthreads();
    for (int off = 1; off < SCAN_B; off <<= 1) {
        int x = (t >= off) ? sh[t - off] : 0;
        __syncthreads();
        sh[t] += x;
        __syncthreads();
    }
    if (t < nb) bsum[t] = sh[t] - v;   // exclusive
}

__global__ void scanC_kernel(int* __restrict__ rp, const int* __restrict__ bsum,
                             int* __restrict__ cur) {
    int i = blockIdx.x * blockDim.x + threadIdx.x;
    if (i < NTOT) {
        int v = rp[i] + bsum[i / SCAN_B];
        rp[i] = v;
        cur[i] = v;
    }
    if (i == 0) rp[NTOT] = 3 * EE;
}

__global__ void fill3_kernel(const int* __restrict__ e0, const int* __restrict__ e1,
                             const int* __restrict__ e2, int* __restrict__ cur,
                             int* __restrict__ perm) {
    int i = blockIdx.x * blockDim.x + threadIdx.x;
    if (i >= 3 * EE) return;
    int r = i / EE, j = i - r * EE;
    const int* e = (r == 0) ? e0 : (r == 1) ? e1 : e2;
    int pos = atomicAdd(&cur[r * NN + e[EE + j]], 1);
    perm[pos] = j;
}

// ---------------- fused per-node attention scores ----------------
template <int C, int HEADS_T>
__global__ void scores_multi(const float* __restrict__ H,
                             const float* __restrict__ a0, const float* __restrict__ a1,
                             const float* __restrict__ a2, const float* __restrict__ a3,
                             float* __restrict__ o0, float* __restrict__ o1,
                             float* __restrict__ o2, float* __restrict__ o3,
                             int nA, int n) {
    int w = (blockIdx.x * blockDim.x + threadIdx.x) >> 5;
    if (w >= n) return;
    int lane = threadIdx.x & 31;
    constexpr int EPL = C / 32;
    constexpr int G = 32 / HEADS_T;

    float h[EPL];
    const float* row = H + (size_t)w * C + lane * EPL;
#pragma unroll
    for (int j = 0; j < EPL; j += 4) {
        float4 v = *(const float4*)(row + j);
        h[j] = v.x; h[j + 1] = v.y; h[j + 2] = v.z; h[j + 3] = v.w;
    }
    const float* av[4] = {a0, a1, a2, a3};
    float* ov[4] = {o0, o1, o2, o3};
#pragma unroll
    for (int k = 0; k < 4; k++) {
        if (k >= nA) break;
        const float* a = av[k] + lane * EPL;
        float s = 0.f;
#pragma unroll
        for (int j = 0; j < EPL; j += 4) {
            float4 v = *(const float4*)(a + j);
            s += h[j] * v.x + h[j + 1] * v.y + h[j + 2] * v.z + h[j + 3] * v.w;
        }
#pragma unroll
        for (int off = 1; off < G; off <<= 1) s += __shfl_xor_sync(0xffffffffu, s, off);
        if ((lane & (G - 1)) == 0) ov[k][w * HEADS_T + lane / G] = s;
    }
}

// ---------------- fused softmax + CSR gather ----------------
__device__ __forceinline__ float lrelu02(float x) { return x >= 0.f ? x : 0.2f * x; }

// warp per dst node: single pass computes exp weights, denominator, and weighted
// feature aggregation in registers; relu on store.
template <int C, int HEADS_T>
__global__ void csr_gather_fused(const int* __restrict__ ei,
                                 const int* __restrict__ rp, const int* __restrict__ perm,
                                 const float* __restrict__ ss, const float* __restrict__ sd,
                                 const float* __restrict__ Hsrc, float* __restrict__ agg) {
    int w = (blockIdx.x * blockDim.x + threadIdx.x) >> 5;
    if (w >= NN) return;
    int lane = threadIdx.x & 31;
    constexpr int EPL = C / 32;
    int h = (HEADS_T == 1) ? 0 : (lane >> 2);
    float sdh = __ldg(&sd[w * HEADS_T + h]);

    float acc[EPL];
#pragma unroll
    for (int j = 0; j < EPL; j++) acc[j] = 0.f;
    float den = 0.f;

    int beg = __ldg(&rp[w]), end = __ldg(&rp[w + 1]);
    const float* base = Hsrc + (size_t)lane * EPL;
    int s0 = 0;
    if (beg < end) s0 = __ldg(&ei[__ldg(&perm[beg])]);
    for (int p = beg; p < end; p++) {
        int s = s0;
        if (p + 1 < end) s0 = __ldg(&ei[__ldg(&perm[p + 1])]);   // prefetch next src
        float al = lrelu02(__ldg(&ss[s * HEADS_T + h]) + sdh);
        float ex = __expf(fminf(al, 80.f));
        den += ex;
        const float* src = base + (size_t)s * C;
#pragma unroll
        for (int j = 0; j < EPL; j += 4) {
            float4 v = *(const float4*)(src + j);
            acc[j]     += ex * v.x;
            acc[j + 1] += ex * v.y;
            acc[j + 2] += ex * v.z;
            acc[j + 3] += ex * v.w;
        }
    }
    float inv = 1.f / (den + 1e-16f);
    float* dst = agg + (size_t)w * C + lane * EPL;
#pragma unroll
    for (int j = 0; j < EPL; j += 4) {
        float4 v;
        v.x = fmaxf(acc[j] * inv, 0.f);
        v.y = fmaxf(acc[j + 1] * inv, 0.f);
        v.z = fmaxf(acc[j + 2] * inv, 0.f);
        v.w = fmaxf(acc[j + 3] * inv, 0.f);
        *(float4*)(dst + j) = v;
    }
}

// ---------------- small kernels ----------------
__global__ void semantic_weights_kernel(const float* __restrict__ colsum,
                                        const float* __restrict__ q,
                                        int C, float invn, float* __restrict__ w) {
    __shared__ float sh0[256], sh1[256];
    int t = threadIdx.x;
    float s0 = 0.f, s1 = 0.f;
    for (int c = t; c < C; c += blockDim.x) {
        float qc = q[c];
        s0 += qc * colsum[c];
        s1 += qc * colsum[C + c];
    }
    sh0[t] = s0; sh1[t] = s1;
    __syncthreads();
    for (int o = blockDim.x / 2; o > 0; o >>= 1) {
        if (t < o) { sh0[t] += sh0[t + o]; sh1[t] += sh1[t + o]; }
        __syncthreads();
    }
    if (t == 0) {
        float a = sh0[0] * invn, b = sh1[0] * invn;
        float m = fmaxf(a, b);
        float ea = expf(a - m), eb = expf(b - m);
        float inv = 1.f / (ea + eb);
        w[0] = ea * inv; w[1] = eb * inv;
    }
}

// out = l2norm(w0*A + w1*B) per row of 128 (warp per row)
__global__ void l2norm_combined_kernel(const float* __restrict__ A, const float* __restrict__ B,
                                       const float* __restrict__ w, float* __restrict__ out,
                                       int n) {
    int r = (blockIdx.x * blockDim.x + threadIdx.x) >> 5;
    if (r >= n) return;
    int lane = threadIdx.x & 31;
    float w0 = w[0], w1 = w[1];
    float4 a = *(const float4*)(A + (size_t)r * 128 + lane * 4);
    float4 b = *(const float4*)(B + (size_t)r * 128 + lane * 4);
    float4 v;
    v.x = w0 * a.x + w1 * b.x;
    v.y = w0 * a.y + w1 * b.y;
    v.z = w0 * a.z + w1 * b.z;
    v.w = w0 * a.w + w1 * b.w;
    float s = v.x * v.x + v.y * v.y + v.z * v.z + v.w * v.w;
#pragma unroll
    for (int off = 16; off > 0; off >>= 1) s += __shfl_xor_sync(0xffffffffu, s, off);
    float inv = 1.f / fmaxf(sqrtf(s), 1e-12f);
    v.x *= inv; v.y *= inv; v.z *= inv; v.w *= inv;
    *(float4*)(out + (size_t)r * 128 + lane * 4) = v;
}

__global__ void l2norm_kernel(const float* __restrict__ in, float* __restrict__ out, int n) {
    int r = (blockIdx.x * blockDim.x + threadIdx.x) >> 5;
    if (r >= n) return;
    int lane = threadIdx.x & 31;
    float4 v = *(const float4*)(in + (size_t)r * 128 + lane * 4);
    float s = v.x * v.x + v.y * v.y + v.z * v.z + v.w * v.w;
#pragma unroll
    for (int off = 16; off > 0; off >>= 1) s += __shfl_xor_sync(0xffffffffu, s, off);
    float inv = 1.f / fmaxf(sqrtf(s), 1e-12f);
    v.x *= inv; v.y *= inv; v.z *= inv; v.w *= inv;
    *(float4*)(out + (size_t)r * 128 + lane * 4) = v;
}

// ---------------- host orchestration ----------------
enum {
    L_XP, L_XA, L_W0P, L_B0P, L_W0A, L_B0A,
    L_A0S_W, L_A0D_W, L_A0S_WB, L_A0D_WB, L_A0S_C, L_A0D_C,
    L_WK0, L_BK0, L_Q0,
    L_W1P, L_B1P, L_W1A, L_B1A,
    L_A1S_W, L_A1D_W, L_A1S_WB, L_A1D_WB, L_A1S_C, L_A1D_C,
    L_WK1, L_BK1, L_Q1, L_EIW, L_EIWB, L_EIC, L_COUNT
};

extern "C" void kernel_launch(void* const* d_in, const int* in_sizes, int n_in,
                              void* d_out, int out_size) {
    static const int mapSig[L_COUNT] = {
        0, 1, 2, 3, 4, 5, 6, 7, 8, 9, 10, 11, 12, 13, 14,
        15, 16, 17, 18, 19, 20, 21, 22, 23, 24, 25, 26, 27, 28, 29, 30};
    static const int mapDict[L_COUNT] = {
        0, 1, 5, 6, 7, 8, 9, 10, 11, 12, 13, 14, 15, 16, 17,
        18, 19, 20, 21, 22, 23, 24, 25, 26, 27, 28, 29, 30, 2, 3, 4};
    const int* mp = (n_in > 2 && in_sizes[2] == 2 * EE) ? mapDict : mapSig;

    const float* in_f[L_COUNT];
    for (int i = 0; i < L_COUNT; i++) in_f[i] = (const float*)d_in[mp[i]];
    const int* ei[3] = {(const int*)d_in[mp[L_EIW]],
                        (const int*)d_in[mp[L_EIWB]],
                        (const int*)d_in[mp[L_EIC]]};

    float *H0P, *H0A, *SC;
    float *AGG0a, *AGG0b, *AGG0c;
    float *H1P, *H1A, *AGG1a, *AGG1b, *AGG1c, *COLSUM, *W2;
    int *RP, *PERM, *CNT, *CUR, *BSUM;
    cudaGetSymbolAddress((void**)&H0P, g_H0P);
    cudaGetSymbolAddress((void**)&H0A, g_H0A);
    cudaGetSymbolAddress((void**)&SC, g_SC);
    cudaGetSymbolAddress((void**)&AGG0a, g_AGG0a);
    cudaGetSymbolAddress((void**)&AGG0b, g_AGG0b);
    cudaGetSymbolAddress((void**)&AGG0c, g_AGG0c);
    cudaGetSymbolAddress((void**)&H1P, g_H1P);
    cudaGetSymbolAddress((void**)&H1A, g_H1A);
    cudaGetSymbolAddress((void**)&AGG1a, g_AGG1a);
    cudaGetSymbolAddress((void**)&AGG1b, g_AGG1b);
    cudaGetSymbolAddress((void**)&AGG1c, g_AGG1c);
    cudaGetSymbolAddress((void**)&COLSUM, g_COLSUM);
    cudaGetSymbolAddress((void**)&W2, g_W2);
    cudaGetSymbolAddress((void**)&RP, g_RP);
    cudaGetSymbolAddress((void**)&PERM, g_PERM);
    cudaGetSymbolAddress((void**)&CNT, g_CNT);
    cudaGetSymbolAddress((void**)&CUR, g_CUR);
    cudaGetSymbolAddress((void**)&BSUM, g_BSUM);

    float* S0 = SC + 0 * (NN * HEADS);
    float* S1 = SC + 1 * (NN * HEADS);
    float* S2 = SC + 2 * (NN * HEADS);
    float* S3 = SC + 3 * (NN * HEADS);
    float* S4 = SC + 4 * (NN * HEADS);
    float* S5 = SC + 5 * (NN * HEADS);
    float* W2a = W2;       // layer0 semantic weights
    float* W2b = W2 + 2;   // layer1 semantic weights

    const int TPB = 256;
    dim3 gGemm256(2, (NN + 127) / 128);
    dim3 gGemm128(1, (NN + 127) / 128);
    int warpBlocks = (NN * 32 + TPB - 1) / TPB;
    int scoreBlocks = (NN + 7) / 8;

    // ======== unified CSR build (edges shared by both layers) ========
    cudaMemsetAsync(CNT, 0, NTOT * sizeof(int));
    hist3_kernel<<<(3 * EE + TPB - 1) / TPB, TPB>>>(ei[0], ei[1], ei[2], CNT);
    scanA_kernel<<<NBLK3, SCAN_B>>>(CNT, RP, BSUM);
    scanB_kernel<<<1, SCAN_B>>>(BSUM, NBLK3);
    scanC_kernel<<<(NTOT + TPB - 1) / TPB, TPB>>>(RP, BSUM, CUR);
    fill3_kernel<<<(3 * EE + TPB - 1) / TPB, TPB>>>(ei[0], ei[1], ei[2], CUR, PERM);

    // ======== Layer 0 ========
    mma_gemm<0, 0><<<gGemm256, TPB>>>(NN, HID, IN_DIM,
        in_f[L_XP], nullptr, in_f[L_W0P], in_f[L_B0P], H0P, nullptr);
    mma_gemm<0, 0><<<gGemm256, TPB>>>(NN, HID, IN_DIM,
        in_f[L_XA], nullptr, in_f[L_W0A], in_f[L_B0A], H0A, nullptr);

    scores_multi<HID, HEADS><<<scoreBlocks, TPB>>>(H0P,
        in_f[L_A0D_W], in_f[L_A0S_WB], in_f[L_A0S_C], in_f[L_A0D_C],
        S1, S2, S4, S5, 4, NN);
    scores_multi<HID, HEADS><<<scoreBlocks, TPB>>>(H0A,
        in_f[L_A0S_W], in_f[L_A0D_WB], in_f[L_A0S_W], in_f[L_A0S_W],
        S0, S3, S0, S0, 2, NN);

    csr_gather_fused<HID, HEADS><<<warpBlocks, TPB>>>(ei[0], RP + 0 * NN, PERM, S0, S1, H0A, AGG0a);
    csr_gather_fused<HID, HEADS><<<warpBlocks, TPB>>>(ei[1], RP + 1 * NN, PERM, S2, S3, H0P, AGG0b);
    csr_gather_fused<HID, HEADS><<<warpBlocks, TPB>>>(ei[2], RP + 2 * NN, PERM, S4, S5, H0P, AGG0c);

    cudaMemsetAsync(COLSUM, 0, 2 * HID * sizeof(float));
    mma_gemm<1, 0><<<gGemm256, TPB>>>(NN, HID, HID,
        AGG0a, nullptr, in_f[L_WK0], in_f[L_BK0], COLSUM, nullptr);
    mma_gemm<1, 0><<<gGemm256, TPB>>>(NN, HID, HID,
        AGG0c, nullptr, in_f[L_WK0], in_f[L_BK0], COLSUM + HID, nullptr);
    semantic_weights_kernel<<<1, 256>>>(COLSUM, in_f[L_Q0], HID, 1.f / NN, W2a);

    // ======== Layer 1 ========
    // paper projection with fused layer0 semantic combine: A' = w0*AGG0a + w1*AGG0c
    mma_gemm<0, 1><<<gGemm128, TPB>>>(NN, OUT_DIM, HID,
        AGG0a, AGG0c, in_f[L_W1P], in_f[L_B1P], H1P, W2a);
    mma_gemm<0, 0><<<gGemm128, TPB>>>(NN, OUT_DIM, HID,
        AGG0b, nullptr, in_f[L_W1A], in_f[L_B1A], H1A, nullptr);

    scores_multi<OUT_DIM, 1><<<scoreBlocks, TPB>>>(H1P,
        in_f[L_A1D_W], in_f[L_A1S_WB], in_f[L_A1S_C], in_f[L_A1D_C],
        S1, S2, S4, S5, 4, NN);
    scores_multi<OUT_DIM, 1><<<scoreBlocks, TPB>>>(H1A,
        in_f[L_A1S_W], in_f[L_A1D_WB], in_f[L_A1S_W], in_f[L_A1S_W],
        S0, S3, S0, S0, 2, NN);

    csr_gather_fused<OUT_DIM, 1><<<warpBlocks, TPB>>>(ei[0], RP + 0 * NN, PERM, S0, S1, H1A, AGG1a);
    csr_gather_fused<OUT_DIM, 1><<<warpBlocks, TPB>>>(ei[1], RP + 1 * NN, PERM, S2, S3, H1P, AGG1b);
    csr_gather_fused<OUT_DIM, 1><<<warpBlocks, TPB>>>(ei[2], RP + 2 * NN, PERM, S4, S5, H1P, AGG1c);

    cudaMemsetAsync(COLSUM, 0, 2 * OUT_DIM * sizeof(float));
    mma_gemm<1, 0><<<gGemm128, TPB>>>(NN, OUT_DIM, OUT_DIM,
        AGG1a, nullptr, in_f[L_WK1], in_f[L_BK1], COLSUM, nullptr);
    mma_gemm<1, 0><<<gGemm128, TPB>>>(NN, OUT_DIM, OUT_DIM,
        AGG1c, nullptr, in_f[L_WK1], in_f[L_BK1], COLSUM + OUT_DIM, nullptr);
    semantic_weights_kernel<<<1, 256>>>(COLSUM, in_f[L_Q1], OUT_DIM, 1.f / NN, W2b);

    // ======== outputs: paper = l2n(w0*AGG1a + w1*AGG1c), author = l2n(AGG1b) ========
    float* out = (float*)d_out;
    int l2Blocks = (NN + 7) / 8;
    l2norm_combined_kernel<<<l2Blocks, TPB>>>(AGG1a, AGG1c, W2b, out, NN);
    l2norm_kernel<<<l2Blocks, TPB>>>(AGG1b, out + (size_t)NN * OUT_DIM, NN);
}